// round 5
// baseline (speedup 1.0000x reference)
#include <cuda_runtime.h>

// ---------------------------------------------------------------------------
// FixedSimpleGNN: 3-layer MPNN, N=100000 nodes, E=1000000 edges, H=64.
//
// Key algebraic optimization: the message MLP's first layer acts on
// concat(h[src], h[dst]) @ W1  ==  h[src] @ W1_top + h[dst] @ W1_bot,
// so we precompute a_s = h@W1_top and a_d = h@W1_bot per NODE (1e5) instead
// of per EDGE (1e6). The per-edge work is then:
//     hidden = relu(a_s[src] + a_d[dst] + b1)        (gather + add)
//     m      = relu(hidden @ W2 + b2)                (64x64 GEMM, fp32x2 FMA)
//     agg[dst] += m                                  (float4 atomics)
// ---------------------------------------------------------------------------

#define NMAX 100000
#define EMAX 1000000

typedef unsigned long long ull;

// scratch (static device memory; no allocations allowed)
__device__ float g_h  [NMAX * 64];
__device__ float g_as [NMAX * 64];
__device__ float g_ad [NMAX * 64];
__device__ float g_agg[NMAX * 64];
__device__ float g_cnt[NMAX];
__device__ float g_inv[NMAX];

// ---- packed fp32x2 helpers (Blackwell FFMA2) ------------------------------
__device__ __forceinline__ ull ffma2(ull a, ull b, ull c) {
    ull d;
    asm("fma.rn.f32x2 %0, %1, %2, %3;" : "=l"(d) : "l"(a), "l"(b), "l"(c));
    return d;
}
__device__ __forceinline__ ull pk2(float x) {
    ull r;
    asm("mov.b64 %0, {%1, %1};" : "=l"(r) : "f"(x));
    return r;
}
__device__ __forceinline__ float2 upk2(ull v) {
    float2 f;
    asm("mov.b64 {%0, %1}, %2;" : "=f"(f.x), "=f"(f.y) : "l"(v));
    return f;
}

// ---------------------------------------------------------------------------
// degree counts
// ---------------------------------------------------------------------------
__global__ void k_zero_cnt(int N) {
    int i = blockIdx.x * blockDim.x + threadIdx.x;
    if (i < N) g_cnt[i] = 0.f;
}
__global__ void k_count(const int* __restrict__ dst, int E) {
    int e = blockIdx.x * blockDim.x + threadIdx.x;
    if (e < E) atomicAdd(&g_cnt[dst[e]], 1.f);
}
__global__ void k_inv(int N) {
    int i = blockIdx.x * blockDim.x + threadIdx.x;
    if (i < N) g_inv[i] = 1.f / fmaxf(g_cnt[i], 1.f);
}

// ---------------------------------------------------------------------------
// encoder: h = relu(relu(x @ w1 + b1) @ w2 + b2), x is [N,5]
// thread-per-node; weights in smem.
// ---------------------------------------------------------------------------
__global__ __launch_bounds__(128) void k_encoder(
    const float* __restrict__ x,
    const float* __restrict__ w1, const float* __restrict__ b1,
    const float* __restrict__ w2, const float* __restrict__ b2, int N)
{
    __shared__ float s_w1[5 * 64];
    __shared__ float s_w2[64 * 64];
    __shared__ float s_b1[64], s_b2[64];
    int tid = threadIdx.x;
    for (int i = tid; i < 5 * 64; i += 128)  s_w1[i] = w1[i];
    for (int i = tid; i < 64 * 64; i += 128) s_w2[i] = w2[i];
    if (tid < 64) { s_b1[tid] = b1[tid]; s_b2[tid] = b2[tid]; }
    __syncthreads();

    int n = blockIdx.x * 128 + tid;
    if (n >= N) return;

    float xv[5];
#pragma unroll
    for (int k = 0; k < 5; k++) xv[k] = x[(size_t)n * 5 + k];

    float hid[64];
#pragma unroll 4
    for (int j = 0; j < 64; j++) {
        float acc = s_b1[j];
#pragma unroll
        for (int k = 0; k < 5; k++) acc = fmaf(xv[k], s_w1[k * 64 + j], acc);
        hid[j] = fmaxf(acc, 0.f);
    }
#pragma unroll 4
    for (int j = 0; j < 64; j++) {
        float acc = s_b2[j];
#pragma unroll
        for (int k = 0; k < 64; k++) acc = fmaf(hid[k], s_w2[k * 64 + j], acc);
        g_h[(size_t)n * 64 + j] = fmaxf(acc, 0.f);
    }
}

// ---------------------------------------------------------------------------
// k_pre: per layer. a_s||a_d = h @ W' where W' is [64,128]:
//   W'[k][j] = w1[k][j]       (j <  64)  -> a_s
//   W'[k][j] = w1[64+k][j-64] (j >= 64)  -> a_d
// Also zeroes g_agg. 256 threads, 128 nodes/block, thread tile 8x8.
// ---------------------------------------------------------------------------
__global__ __launch_bounds__(256) void k_pre(const float* __restrict__ w1, int N)
{
    extern __shared__ float sm[];
    float* s_h = sm;              // 128 * 65
    float* s_w = sm + 128 * 65;   // 64 * 128
    int tid = threadIdx.x;
    int n0 = blockIdx.x * 128;

    for (int i = tid; i < 64 * 128; i += 256) {
        int k = i >> 7, j = i & 127;
        s_w[i] = (j < 64) ? w1[k * 64 + j] : w1[(64 + k) * 64 + (j - 64)];
    }
    for (int i = tid; i < 128 * 64; i += 256) {
        int r = i >> 6, k = i & 63;
        int n = n0 + r;
        s_h[r * 65 + k] = (n < N) ? g_h[(size_t)n * 64 + k] : 0.f;
    }
    __syncthreads();

    int r0 = (tid >> 4) * 8;
    int c0 = (tid & 15) * 8;
    float acc[8][8];
#pragma unroll
    for (int r = 0; r < 8; r++)
#pragma unroll
        for (int c = 0; c < 8; c++) acc[r][c] = 0.f;

#pragma unroll 4
    for (int k = 0; k < 64; k++) {
        float4 b0 = *(const float4*)(s_w + k * 128 + c0);
        float4 b1v = *(const float4*)(s_w + k * 128 + c0 + 4);
#pragma unroll
        for (int r = 0; r < 8; r++) {
            float a = s_h[(r0 + r) * 65 + k];
            acc[r][0] = fmaf(a, b0.x, acc[r][0]);
            acc[r][1] = fmaf(a, b0.y, acc[r][1]);
            acc[r][2] = fmaf(a, b0.z, acc[r][2]);
            acc[r][3] = fmaf(a, b0.w, acc[r][3]);
            acc[r][4] = fmaf(a, b1v.x, acc[r][4]);
            acc[r][5] = fmaf(a, b1v.y, acc[r][5]);
            acc[r][6] = fmaf(a, b1v.z, acc[r][6]);
            acc[r][7] = fmaf(a, b1v.w, acc[r][7]);
        }
    }

#pragma unroll
    for (int r = 0; r < 8; r++) {
        int n = n0 + r0 + r;
        if (n >= N) break;
        float4 v0 = make_float4(acc[r][0], acc[r][1], acc[r][2], acc[r][3]);
        float4 v1 = make_float4(acc[r][4], acc[r][5], acc[r][6], acc[r][7]);
        if (c0 < 64) {
            *(float4*)(g_as + (size_t)n * 64 + c0) = v0;
            *(float4*)(g_as + (size_t)n * 64 + c0 + 4) = v1;
            float4 z = make_float4(0.f, 0.f, 0.f, 0.f);
            *(float4*)(g_agg + (size_t)n * 64 + c0) = z;
            *(float4*)(g_agg + (size_t)n * 64 + c0 + 4) = z;
        } else {
            *(float4*)(g_ad + (size_t)n * 64 + (c0 - 64)) = v0;
            *(float4*)(g_ad + (size_t)n * 64 + (c0 - 64) + 4) = v1;
        }
    }
}

// ---------------------------------------------------------------------------
// k_edge: per edge: hidden = relu(a_s[src]+a_d[dst]+b1); m = relu(hidden@W2+b2);
// agg[dst] += m. 128 threads, 128 edges/block, thread tile 8x8, fp32x2 FMA.
// ---------------------------------------------------------------------------
__global__ __launch_bounds__(128) void k_edge(
    const int* __restrict__ src, const int* __restrict__ dst,
    const float* __restrict__ b1, const float* __restrict__ w2,
    const float* __restrict__ b2, int E)
{
    extern __shared__ float sm[];
    float* s_hid = sm;             // 128 * 65
    float* s_w2  = sm + 128 * 65;  // 64 * 64
    __shared__ float s_b1[64], s_b2[64];
    __shared__ int s_src[128], s_dst[128];
    int tid = threadIdx.x;
    int e0 = blockIdx.x * 128;

    for (int i = tid; i < 4096; i += 128) s_w2[i] = w2[i];
    if (tid < 64) { s_b1[tid] = b1[tid]; s_b2[tid] = b2[tid]; }
    {
        int e = e0 + tid;
        bool v = (e < E);
        s_src[tid] = v ? src[e] : -1;
        s_dst[tid] = v ? dst[e] : -1;
    }
    __syncthreads();

    // gather + hidden: 128 edges x 64 = 8192 elems / 128 threads
#pragma unroll 8
    for (int i = 0; i < 64; i++) {
        int idx = i * 128 + tid;
        int e = idx >> 6, j = idx & 63;
        int s = s_src[e];
        float v = 0.f;
        if (s >= 0) {
            int d = s_dst[e];
            v = fmaxf(__ldg(g_as + (size_t)s * 64 + j) +
                      __ldg(g_ad + (size_t)d * 64 + j) + s_b1[j], 0.f);
        }
        s_hid[e * 65 + j] = v;
    }
    __syncthreads();

    int r0 = (tid >> 3) * 8;   // 16 row groups of 8 edges
    int c0 = (tid & 7) * 8;    // 8 col groups of 8 cols
    ull acc[8][4];
#pragma unroll
    for (int r = 0; r < 8; r++)
#pragma unroll
        for (int c = 0; c < 4; c++) acc[r][c] = 0ull;

#pragma unroll 4
    for (int k = 0; k < 64; k++) {
        ulonglong2 bA = *(const ulonglong2*)(s_w2 + k * 64 + c0);
        ulonglong2 bB = *(const ulonglong2*)(s_w2 + k * 64 + c0 + 4);
#pragma unroll
        for (int r = 0; r < 8; r++) {
            ull aa = pk2(s_hid[(r0 + r) * 65 + k]);
            acc[r][0] = ffma2(aa, bA.x, acc[r][0]);
            acc[r][1] = ffma2(aa, bA.y, acc[r][1]);
            acc[r][2] = ffma2(aa, bB.x, acc[r][2]);
            acc[r][3] = ffma2(aa, bB.y, acc[r][3]);
        }
    }

#pragma unroll
    for (int r = 0; r < 8; r++) {
        int d = s_dst[r0 + r];
        if (d < 0) continue;
        float2 p0 = upk2(acc[r][0]);
        float2 p1 = upk2(acc[r][1]);
        float2 p2 = upk2(acc[r][2]);
        float2 p3 = upk2(acc[r][3]);
        float4 v0, v1;
        v0.x = fmaxf(p0.x + s_b2[c0 + 0], 0.f);
        v0.y = fmaxf(p0.y + s_b2[c0 + 1], 0.f);
        v0.z = fmaxf(p1.x + s_b2[c0 + 2], 0.f);
        v0.w = fmaxf(p1.y + s_b2[c0 + 3], 0.f);
        v1.x = fmaxf(p2.x + s_b2[c0 + 4], 0.f);
        v1.y = fmaxf(p2.y + s_b2[c0 + 5], 0.f);
        v1.z = fmaxf(p3.x + s_b2[c0 + 6], 0.f);
        v1.w = fmaxf(p3.y + s_b2[c0 + 7], 0.f);
        atomicAdd((float4*)(g_agg + (size_t)d * 64 + c0), v0);
        atomicAdd((float4*)(g_agg + (size_t)d * 64 + c0 + 4), v1);
    }
}

// ---------------------------------------------------------------------------
// k_upd: h = mlp2(concat(h, agg*inv), uw1, ub1, uw2, ub2) in place.
// 256 threads, 128 nodes/block, thread tile 8x4.
// ---------------------------------------------------------------------------
__global__ __launch_bounds__(256) void k_upd(
    const float* __restrict__ w1, const float* __restrict__ b1,
    const float* __restrict__ w2, const float* __restrict__ b2, int N)
{
    extern __shared__ float sm[];
    float* s_in = sm;               // comb 128*129, later hidden 128*65
    float* s_w  = sm + 128 * 129;   // 128*64 (w1), later 64*64 (w2)
    __shared__ float s_b1[64], s_b2[64];
    int tid = threadIdx.x;
    int n0 = blockIdx.x * 128;

    if (tid < 64) { s_b1[tid] = b1[tid]; s_b2[tid] = b2[tid]; }
    for (int i = tid; i < 128 * 64; i += 256) s_w[i] = w1[i];
    for (int i = tid; i < 128 * 128; i += 256) {
        int r = i >> 7, k = i & 127;
        int n = n0 + r;
        float v = 0.f;
        if (n < N)
            v = (k < 64) ? g_h[(size_t)n * 64 + k]
                         : g_agg[(size_t)n * 64 + (k - 64)] * g_inv[n];
        s_in[r * 129 + k] = v;
    }
    __syncthreads();

    int r0 = (tid >> 4) * 8;
    int c0 = (tid & 15) * 4;
    float acc[8][4];
#pragma unroll
    for (int r = 0; r < 8; r++)
#pragma unroll
        for (int c = 0; c < 4; c++) acc[r][c] = 0.f;

#pragma unroll 4
    for (int k = 0; k < 128; k++) {
        float4 b = *(const float4*)(s_w + k * 64 + c0);
#pragma unroll
        for (int r = 0; r < 8; r++) {
            float a = s_in[(r0 + r) * 129 + k];
            acc[r][0] = fmaf(a, b.x, acc[r][0]);
            acc[r][1] = fmaf(a, b.y, acc[r][1]);
            acc[r][2] = fmaf(a, b.z, acc[r][2]);
            acc[r][3] = fmaf(a, b.w, acc[r][3]);
        }
    }
    __syncthreads();

    // write hidden (relu) into overlay (stride 65), stage w2
#pragma unroll
    for (int r = 0; r < 8; r++)
#pragma unroll
        for (int c = 0; c < 4; c++)
            s_in[(r0 + r) * 65 + c0 + c] = fmaxf(acc[r][c] + s_b1[c0 + c], 0.f);
    for (int i = tid; i < 64 * 64; i += 256) s_w[i] = w2[i];
    __syncthreads();

    float acc2[8][4];
#pragma unroll
    for (int r = 0; r < 8; r++)
#pragma unroll
        for (int c = 0; c < 4; c++) acc2[r][c] = 0.f;

#pragma unroll 4
    for (int k = 0; k < 64; k++) {
        float4 b = *(const float4*)(s_w + k * 64 + c0);
#pragma unroll
        for (int r = 0; r < 8; r++) {
            float a = s_in[(r0 + r) * 65 + k];
            acc2[r][0] = fmaf(a, b.x, acc2[r][0]);
            acc2[r][1] = fmaf(a, b.y, acc2[r][1]);
            acc2[r][2] = fmaf(a, b.z, acc2[r][2]);
            acc2[r][3] = fmaf(a, b.w, acc2[r][3]);
        }
    }
#pragma unroll
    for (int r = 0; r < 8; r++) {
        int n = n0 + r0 + r;
        if (n >= N) break;
        float4 v;
        v.x = fmaxf(acc2[r][0] + s_b2[c0 + 0], 0.f);
        v.y = fmaxf(acc2[r][1] + s_b2[c0 + 1], 0.f);
        v.z = fmaxf(acc2[r][2] + s_b2[c0 + 2], 0.f);
        v.w = fmaxf(acc2[r][3] + s_b2[c0 + 3], 0.f);
        *(float4*)(g_h + (size_t)n * 64 + c0) = v;
    }
}

// ---------------------------------------------------------------------------
// k_out: pred = relu(h@ow1+ob1)@ow2+ob2; out = 2*pi*sigmoid(pred), [N,3]
// ---------------------------------------------------------------------------
__global__ __launch_bounds__(128) void k_out(
    const float* __restrict__ w1, const float* __restrict__ b1,
    const float* __restrict__ w2, const float* __restrict__ b2,
    float* __restrict__ out, int N)
{
    extern __shared__ float sm[];
    float* s_h  = sm;             // 128 * 65
    float* s_w1 = sm + 128 * 65;  // 64 * 64
    __shared__ float s_b1[64], s_w2[64 * 3], s_b2[3];
    int tid = threadIdx.x;
    int n0 = blockIdx.x * 128;

    for (int i = tid; i < 4096; i += 128) s_w1[i] = w1[i];
    if (tid < 64) s_b1[tid] = b1[tid];
    for (int i = tid; i < 192; i += 128) s_w2[i] = w2[i];
    if (tid < 3) s_b2[tid] = b2[tid];
    for (int i = tid; i < 128 * 64; i += 128) {
        int r = i >> 6, k = i & 63;
        int n = n0 + r;
        s_h[r * 65 + k] = (n < N) ? g_h[(size_t)n * 64 + k] : 0.f;
    }
    __syncthreads();

    int n = n0 + tid;
    if (n >= N) return;

    float hrow[64];
#pragma unroll
    for (int k = 0; k < 64; k++) hrow[k] = s_h[tid * 65 + k];

    float hid[64];
#pragma unroll 4
    for (int j = 0; j < 64; j++) {
        float acc = s_b1[j];
#pragma unroll
        for (int k = 0; k < 64; k++) acc = fmaf(hrow[k], s_w1[k * 64 + j], acc);
        hid[j] = fmaxf(acc, 0.f);
    }
#pragma unroll
    for (int c = 0; c < 3; c++) {
        float acc = s_b2[c];
#pragma unroll
        for (int k = 0; k < 64; k++) acc = fmaf(hid[k], s_w2[k * 3 + c], acc);
        out[(size_t)n * 3 + c] = 6.283185307179586f / (1.f + expf(-acc));
    }
}

// ---------------------------------------------------------------------------
extern "C" void kernel_launch(void* const* d_in, const int* in_sizes, int n_in,
                              void* d_out, int out_size)
{
    const float* x      = (const float*)d_in[0];
    const int*   ei     = (const int*)  d_in[1];
    const float* enc_w1 = (const float*)d_in[2];
    const float* enc_b1 = (const float*)d_in[3];
    const float* enc_w2 = (const float*)d_in[4];
    const float* enc_b2 = (const float*)d_in[5];
    const float* msg_w1 = (const float*)d_in[6];
    const float* msg_b1 = (const float*)d_in[7];
    const float* msg_w2 = (const float*)d_in[8];
    const float* msg_b2 = (const float*)d_in[9];
    const float* upd_w1 = (const float*)d_in[10];
    const float* upd_b1 = (const float*)d_in[11];
    const float* upd_w2 = (const float*)d_in[12];
    const float* upd_b2 = (const float*)d_in[13];
    const float* out_w1 = (const float*)d_in[14];
    const float* out_b1 = (const float*)d_in[15];
    const float* out_w2 = (const float*)d_in[16];
    const float* out_b2 = (const float*)d_in[17];

    int N = in_sizes[0] / 5;
    int E = in_sizes[1] / 2;
    if (N > NMAX) N = NMAX;
    if (E > EMAX) E = EMAX;
    const int* src = ei;
    const int* dstp = ei + E;

    const int PRE_SM = (128 * 65 + 64 * 128) * 4;   // 66048
    const int EDG_SM = (128 * 65 + 64 * 64) * 4;    // 49664
    const int UPD_SM = (128 * 129 + 128 * 64) * 4;  // 98816
    const int OUT_SM = (128 * 65 + 64 * 64) * 4;    // 49664
    cudaFuncSetAttribute(k_pre,  cudaFuncAttributeMaxDynamicSharedMemorySize, PRE_SM);
    cudaFuncSetAttribute(k_edge, cudaFuncAttributeMaxDynamicSharedMemorySize, EDG_SM);
    cudaFuncSetAttribute(k_upd,  cudaFuncAttributeMaxDynamicSharedMemorySize, UPD_SM);
    cudaFuncSetAttribute(k_out,  cudaFuncAttributeMaxDynamicSharedMemorySize, OUT_SM);

    int nbN256 = (N + 255) / 256;
    int nbE256 = (E + 255) / 256;
    int nbN128 = (N + 127) / 128;
    int nbE128 = (E + 127) / 128;

    k_zero_cnt<<<nbN256, 256>>>(N);
    k_count<<<nbE256, 256>>>(dstp, E);
    k_inv<<<nbN256, 256>>>(N);
    k_encoder<<<nbN128, 128>>>(x, enc_w1, enc_b1, enc_w2, enc_b2, N);

    for (int l = 0; l < 3; l++) {
        k_pre<<<nbN128, 256, PRE_SM>>>(msg_w1 + l * 128 * 64, N);
        k_edge<<<nbE128, 128, EDG_SM>>>(src, dstp,
                                        msg_b1 + l * 64,
                                        msg_w2 + l * 64 * 64,
                                        msg_b2 + l * 64, E);
        k_upd<<<nbN128, 256, UPD_SM>>>(upd_w1 + l * 128 * 64,
                                       upd_b1 + l * 64,
                                       upd_w2 + l * 64 * 64,
                                       upd_b2 + l * 64, N);
    }

    k_out<<<nbN128, 128, OUT_SM>>>(out_w1, out_b1, out_w2, out_b2,
                                   (float*)d_out, N);
}

// round 6
// speedup vs baseline: 1.3303x; 1.3303x over previous
#include <cuda_runtime.h>

// ---------------------------------------------------------------------------
// FixedSimpleGNN: 3-layer MPNN, N=100000, E=1000000, H=64.
//
// Structure:
//   a_s = h @ W1_top, a_d = h @ W1_bot per NODE (factorized concat GEMM)
//   per edge: hidden = relu(a_s[src]+a_d[dst]+b1)
//             m      = relu(hidden @ W2 + b2)   <-- tf32 mma.sync tensor cores
//             agg[dst] += m                     (float4 atomics)
// ---------------------------------------------------------------------------

#define NMAX 100000
#define EMAX 1000000

typedef unsigned int uint;

// scratch (static device memory; no allocations allowed)
__device__ float g_h  [NMAX * 64];
__device__ float g_as [NMAX * 64];
__device__ float g_ad [NMAX * 64];
__device__ float g_agg[NMAX * 64];
__device__ float g_cnt[NMAX];
__device__ float g_inv[NMAX];

__device__ __forceinline__ float to_tf32(float x) {
    uint u;
    asm("cvt.rna.tf32.f32 %0, %1;" : "=r"(u) : "f"(x));
    return __uint_as_float(u);
}

__device__ __forceinline__ void mma_tf32(
    float& c0, float& c1, float& c2, float& c3,
    uint a0, uint a1, uint a2, uint a3, uint b0, uint b1)
{
    asm volatile(
        "mma.sync.aligned.m16n8k8.row.col.f32.tf32.tf32.f32 "
        "{%0,%1,%2,%3}, {%4,%5,%6,%7}, {%8,%9}, {%0,%1,%2,%3};"
        : "+f"(c0), "+f"(c1), "+f"(c2), "+f"(c3)
        : "r"(a0), "r"(a1), "r"(a2), "r"(a3), "r"(b0), "r"(b1));
}

// ---------------------------------------------------------------------------
// degree counts
// ---------------------------------------------------------------------------
__global__ void k_zero_cnt(int N) {
    int i = blockIdx.x * blockDim.x + threadIdx.x;
    if (i < N) g_cnt[i] = 0.f;
}
__global__ void k_count(const int* __restrict__ dst, int E) {
    int e = blockIdx.x * blockDim.x + threadIdx.x;
    if (e < E) atomicAdd(&g_cnt[dst[e]], 1.f);
}
__global__ void k_inv(int N) {
    int i = blockIdx.x * blockDim.x + threadIdx.x;
    if (i < N) g_inv[i] = 1.f / fmaxf(g_cnt[i], 1.f);
}

// ---------------------------------------------------------------------------
// encoder (tiled): h = relu(relu(x @ w1 + b1) @ w2 + b2), x is [N,5]
// 256 threads, 128 nodes/block, thread tile 8x4.
// ---------------------------------------------------------------------------
__global__ __launch_bounds__(256) void k_encoder(
    const float* __restrict__ x,
    const float* __restrict__ w1, const float* __restrict__ b1,
    const float* __restrict__ w2, const float* __restrict__ b2, int N)
{
    extern __shared__ float sm[];
    float* s_hid = sm;             // 128 * 65
    float* s_w2  = sm + 128 * 65;  // 64 * 64
    __shared__ float s_w1[5 * 64], s_b1[64], s_b2[64];
    __shared__ float s_x[128 * 6];
    int tid = threadIdx.x;
    int n0 = blockIdx.x * 128;

    for (int i = tid; i < 5 * 64; i += 256)  s_w1[i] = w1[i];
    for (int i = tid; i < 64 * 64; i += 256) s_w2[i] = w2[i];
    if (tid < 64) { s_b1[tid] = b1[tid]; s_b2[tid] = b2[tid]; }
    for (int i = tid; i < 128 * 5; i += 256) {
        int r = i / 5, k = i % 5;
        int n = n0 + r;
        s_x[r * 6 + k] = (n < N) ? x[(size_t)n * 5 + k] : 0.f;
    }
    __syncthreads();

    int r0 = (tid >> 4) * 8;
    int c0 = (tid & 15) * 4;

    float acc[8][4];
#pragma unroll
    for (int r = 0; r < 8; r++)
#pragma unroll
        for (int c = 0; c < 4; c++) acc[r][c] = 0.f;
#pragma unroll
    for (int k = 0; k < 5; k++) {
        float4 b = *(const float4*)(s_w1 + k * 64 + c0);
#pragma unroll
        for (int r = 0; r < 8; r++) {
            float a = s_x[(r0 + r) * 6 + k];
            acc[r][0] = fmaf(a, b.x, acc[r][0]);
            acc[r][1] = fmaf(a, b.y, acc[r][1]);
            acc[r][2] = fmaf(a, b.z, acc[r][2]);
            acc[r][3] = fmaf(a, b.w, acc[r][3]);
        }
    }
#pragma unroll
    for (int r = 0; r < 8; r++)
#pragma unroll
        for (int c = 0; c < 4; c++)
            s_hid[(r0 + r) * 65 + c0 + c] = fmaxf(acc[r][c] + s_b1[c0 + c], 0.f);
    __syncthreads();

    float acc2[8][4];
#pragma unroll
    for (int r = 0; r < 8; r++)
#pragma unroll
        for (int c = 0; c < 4; c++) acc2[r][c] = 0.f;
#pragma unroll 4
    for (int k = 0; k < 64; k++) {
        float4 b = *(const float4*)(s_w2 + k * 64 + c0);
#pragma unroll
        for (int r = 0; r < 8; r++) {
            float a = s_hid[(r0 + r) * 65 + k];
            acc2[r][0] = fmaf(a, b.x, acc2[r][0]);
            acc2[r][1] = fmaf(a, b.y, acc2[r][1]);
            acc2[r][2] = fmaf(a, b.z, acc2[r][2]);
            acc2[r][3] = fmaf(a, b.w, acc2[r][3]);
        }
    }
#pragma unroll
    for (int r = 0; r < 8; r++) {
        int n = n0 + r0 + r;
        if (n >= N) break;
        float4 v;
        v.x = fmaxf(acc2[r][0] + s_b2[c0 + 0], 0.f);
        v.y = fmaxf(acc2[r][1] + s_b2[c0 + 1], 0.f);
        v.z = fmaxf(acc2[r][2] + s_b2[c0 + 2], 0.f);
        v.w = fmaxf(acc2[r][3] + s_b2[c0 + 3], 0.f);
        *(float4*)(g_h + (size_t)n * 64 + c0) = v;
    }
}

// ---------------------------------------------------------------------------
// k_pre: a_s||a_d = h @ [W1_top ; W1_bot] transposed packing. Zeroes g_agg.
// 256 threads, 128 nodes/block, thread tile 8x8. (unchanged, passing)
// ---------------------------------------------------------------------------
__global__ __launch_bounds__(256) void k_pre(const float* __restrict__ w1, int N)
{
    extern __shared__ float sm[];
    float* s_h = sm;              // 128 * 65
    float* s_w = sm + 128 * 65;   // 64 * 128
    int tid = threadIdx.x;
    int n0 = blockIdx.x * 128;

    for (int i = tid; i < 64 * 128; i += 256) {
        int k = i >> 7, j = i & 127;
        s_w[i] = (j < 64) ? w1[k * 64 + j] : w1[(64 + k) * 64 + (j - 64)];
    }
    for (int i = tid; i < 128 * 64; i += 256) {
        int r = i >> 6, k = i & 63;
        int n = n0 + r;
        s_h[r * 65 + k] = (n < N) ? g_h[(size_t)n * 64 + k] : 0.f;
    }
    __syncthreads();

    int r0 = (tid >> 4) * 8;
    int c0 = (tid & 15) * 8;
    float acc[8][8];
#pragma unroll
    for (int r = 0; r < 8; r++)
#pragma unroll
        for (int c = 0; c < 8; c++) acc[r][c] = 0.f;

#pragma unroll 4
    for (int k = 0; k < 64; k++) {
        float4 b0 = *(const float4*)(s_w + k * 128 + c0);
        float4 b1v = *(const float4*)(s_w + k * 128 + c0 + 4);
#pragma unroll
        for (int r = 0; r < 8; r++) {
            float a = s_h[(r0 + r) * 65 + k];
            acc[r][0] = fmaf(a, b0.x, acc[r][0]);
            acc[r][1] = fmaf(a, b0.y, acc[r][1]);
            acc[r][2] = fmaf(a, b0.z, acc[r][2]);
            acc[r][3] = fmaf(a, b0.w, acc[r][3]);
            acc[r][4] = fmaf(a, b1v.x, acc[r][4]);
            acc[r][5] = fmaf(a, b1v.y, acc[r][5]);
            acc[r][6] = fmaf(a, b1v.z, acc[r][6]);
            acc[r][7] = fmaf(a, b1v.w, acc[r][7]);
        }
    }

#pragma unroll
    for (int r = 0; r < 8; r++) {
        int n = n0 + r0 + r;
        if (n >= N) break;
        float4 v0 = make_float4(acc[r][0], acc[r][1], acc[r][2], acc[r][3]);
        float4 v1 = make_float4(acc[r][4], acc[r][5], acc[r][6], acc[r][7]);
        if (c0 < 64) {
            *(float4*)(g_as + (size_t)n * 64 + c0) = v0;
            *(float4*)(g_as + (size_t)n * 64 + c0 + 4) = v1;
            float4 z = make_float4(0.f, 0.f, 0.f, 0.f);
            *(float4*)(g_agg + (size_t)n * 64 + c0) = z;
            *(float4*)(g_agg + (size_t)n * 64 + c0 + 4) = z;
        } else {
            *(float4*)(g_ad + (size_t)n * 64 + (c0 - 64)) = v0;
            *(float4*)(g_ad + (size_t)n * 64 + (c0 - 64) + 4) = v1;
        }
    }
}

// ---------------------------------------------------------------------------
// k_edge (tensor-core v2): 256 threads (8 warps), 128 edges/block.
//   gather + relu -> s_hid (tf32-rounded fp32, stride 68)
//   m = relu(hidden @ W2 + b2) via mma.sync m16n8k8 tf32 (warp = 16 edges)
//   m -> s_hid (reuse), then float4 atomics into g_agg
// ---------------------------------------------------------------------------
#define HS 68   // s_hid stride (floats): A-frag LDS conflict-free
#define WS 72   // s_w2 stride  (floats): B-frag LDS conflict-free
__global__ __launch_bounds__(256) void k_edge(
    const int* __restrict__ src, const int* __restrict__ dst,
    const float* __restrict__ b1, const float* __restrict__ w2,
    const float* __restrict__ b2, int E)
{
    extern __shared__ float sm[];
    float* s_hid = sm;             // 128 * HS
    float* s_w2  = sm + 128 * HS;  // 64 * WS
    __shared__ float s_b1[64], s_b2[64];
    __shared__ int s_src[128], s_dst[128];
    int tid = threadIdx.x;
    int e0 = blockIdx.x * 128;

    for (int i = tid; i < 4096; i += 256) {
        int k = i >> 6, n = i & 63;
        s_w2[k * WS + n] = to_tf32(w2[i]);
    }
    if (tid < 64) { s_b1[tid] = b1[tid]; s_b2[tid] = b2[tid]; }
    if (tid < 128) {
        int e = e0 + tid;
        bool v = (e < E);
        s_src[tid] = v ? src[e] : -1;
        s_dst[tid] = v ? dst[e] : -1;
    }
    __syncthreads();

    // gather + first-layer: 128 edges x 64 = 8192 / 256 threads
#pragma unroll 8
    for (int i = 0; i < 32; i++) {
        int idx = i * 256 + tid;
        int e = idx >> 6, j = idx & 63;
        int s = s_src[e];
        float v = 0.f;
        if (s >= 0) {
            int d = s_dst[e];
            v = fmaxf(__ldg(g_as + (size_t)s * 64 + j) +
                      __ldg(g_ad + (size_t)d * 64 + j) + s_b1[j], 0.f);
        }
        s_hid[e * HS + j] = to_tf32(v);
    }
    __syncthreads();

    // tensor-core GEMM: warp w -> edges [w*16, w*16+16), all 64 cols, K=64
    int warp = tid >> 5, lane = tid & 31;
    int m0 = warp * 16;
    int qrow = lane >> 2;   // 0..7
    int qcol = lane & 3;    // 0..3

    float acc[8][4];
#pragma unroll
    for (int nt = 0; nt < 8; nt++)
#pragma unroll
        for (int c = 0; c < 4; c++) acc[nt][c] = 0.f;

    const float* Ab = s_hid + (m0 + qrow) * HS + qcol;
    const float* Bb = s_w2 + qcol * WS + qrow;

#pragma unroll
    for (int kt = 0; kt < 8; kt++) {
        uint a0 = __float_as_uint(Ab[kt * 8]);
        uint a1 = __float_as_uint(Ab[kt * 8 + 8 * HS]);
        uint a2 = __float_as_uint(Ab[kt * 8 + 4]);
        uint a3 = __float_as_uint(Ab[kt * 8 + 4 + 8 * HS]);
#pragma unroll
        for (int nt = 0; nt < 8; nt++) {
            uint b0 = __float_as_uint(Bb[kt * 8 * WS + nt * 8]);
            uint b1v = __float_as_uint(Bb[kt * 8 * WS + nt * 8 + 4 * WS]);
            mma_tf32(acc[nt][0], acc[nt][1], acc[nt][2], acc[nt][3],
                     a0, a1, a2, a3, b0, b1v);
        }
    }
    __syncthreads();  // all warps done reading s_hid

    // epilogue: bias + relu, m -> s_hid (stride HS)
#pragma unroll
    for (int nt = 0; nt < 8; nt++) {
        int c = nt * 8 + qcol * 2;
        float bx = s_b2[c], by = s_b2[c + 1];
        float2 lo, hi;
        lo.x = fmaxf(acc[nt][0] + bx, 0.f);
        lo.y = fmaxf(acc[nt][1] + by, 0.f);
        hi.x = fmaxf(acc[nt][2] + bx, 0.f);
        hi.y = fmaxf(acc[nt][3] + by, 0.f);
        *(float2*)(s_hid + (m0 + qrow) * HS + c)     = lo;
        *(float2*)(s_hid + (m0 + qrow + 8) * HS + c) = hi;
    }
    __syncthreads();

    // scatter: 128 edges x 16 float4 = 2048 / 256 threads = 8 each
#pragma unroll
    for (int i = 0; i < 8; i++) {
        int lin = i * 256 + tid;
        int e = lin >> 4, q = lin & 15;
        int d = s_dst[e];
        if (d >= 0) {
            float4 v = *(const float4*)(s_hid + e * HS + q * 4);
            atomicAdd((float4*)(g_agg + (size_t)d * 64 + q * 4), v);
        }
    }
}

// ---------------------------------------------------------------------------
// k_upd: h = mlp2(concat(h, agg*inv), uw1, ub1, uw2, ub2) in place. (unchanged)
// ---------------------------------------------------------------------------
__global__ __launch_bounds__(256) void k_upd(
    const float* __restrict__ w1, const float* __restrict__ b1,
    const float* __restrict__ w2, const float* __restrict__ b2, int N)
{
    extern __shared__ float sm[];
    float* s_in = sm;               // comb 128*129, later hidden 128*65
    float* s_w  = sm + 128 * 129;   // 128*64 (w1), later 64*64 (w2)
    __shared__ float s_b1[64], s_b2[64];
    int tid = threadIdx.x;
    int n0 = blockIdx.x * 128;

    if (tid < 64) { s_b1[tid] = b1[tid]; s_b2[tid] = b2[tid]; }
    for (int i = tid; i < 128 * 64; i += 256) s_w[i] = w1[i];
    for (int i = tid; i < 128 * 128; i += 256) {
        int r = i >> 7, k = i & 127;
        int n = n0 + r;
        float v = 0.f;
        if (n < N)
            v = (k < 64) ? g_h[(size_t)n * 64 + k]
                         : g_agg[(size_t)n * 64 + (k - 64)] * g_inv[n];
        s_in[r * 129 + k] = v;
    }
    __syncthreads();

    int r0 = (tid >> 4) * 8;
    int c0 = (tid & 15) * 4;
    float acc[8][4];
#pragma unroll
    for (int r = 0; r < 8; r++)
#pragma unroll
        for (int c = 0; c < 4; c++) acc[r][c] = 0.f;

#pragma unroll 4
    for (int k = 0; k < 128; k++) {
        float4 b = *(const float4*)(s_w + k * 64 + c0);
#pragma unroll
        for (int r = 0; r < 8; r++) {
            float a = s_in[(r0 + r) * 129 + k];
            acc[r][0] = fmaf(a, b.x, acc[r][0]);
            acc[r][1] = fmaf(a, b.y, acc[r][1]);
            acc[r][2] = fmaf(a, b.z, acc[r][2]);
            acc[r][3] = fmaf(a, b.w, acc[r][3]);
        }
    }
    __syncthreads();

#pragma unroll
    for (int r = 0; r < 8; r++)
#pragma unroll
        for (int c = 0; c < 4; c++)
            s_in[(r0 + r) * 65 + c0 + c] = fmaxf(acc[r][c] + s_b1[c0 + c], 0.f);
    for (int i = tid; i < 64 * 64; i += 256) s_w[i] = w2[i];
    __syncthreads();

    float acc2[8][4];
#pragma unroll
    for (int r = 0; r < 8; r++)
#pragma unroll
        for (int c = 0; c < 4; c++) acc2[r][c] = 0.f;

#pragma unroll 4
    for (int k = 0; k < 64; k++) {
        float4 b = *(const float4*)(s_w + k * 64 + c0);
#pragma unroll
        for (int r = 0; r < 8; r++) {
            float a = s_in[(r0 + r) * 65 + k];
            acc2[r][0] = fmaf(a, b.x, acc2[r][0]);
            acc2[r][1] = fmaf(a, b.y, acc2[r][1]);
            acc2[r][2] = fmaf(a, b.z, acc2[r][2]);
            acc2[r][3] = fmaf(a, b.w, acc2[r][3]);
        }
    }
#pragma unroll
    for (int r = 0; r < 8; r++) {
        int n = n0 + r0 + r;
        if (n >= N) break;
        float4 v;
        v.x = fmaxf(acc2[r][0] + s_b2[c0 + 0], 0.f);
        v.y = fmaxf(acc2[r][1] + s_b2[c0 + 1], 0.f);
        v.z = fmaxf(acc2[r][2] + s_b2[c0 + 2], 0.f);
        v.w = fmaxf(acc2[r][3] + s_b2[c0 + 3], 0.f);
        *(float4*)(g_h + (size_t)n * 64 + c0) = v;
    }
}

// ---------------------------------------------------------------------------
// k_out: pred = relu(h@ow1+ob1)@ow2+ob2; out = 2*pi*sigmoid(pred), [N,3]
// ---------------------------------------------------------------------------
__global__ __launch_bounds__(128) void k_out(
    const float* __restrict__ w1, const float* __restrict__ b1,
    const float* __restrict__ w2, const float* __restrict__ b2,
    float* __restrict__ out, int N)
{
    extern __shared__ float sm[];
    float* s_h  = sm;             // 128 * 65
    float* s_w1 = sm + 128 * 65;  // 64 * 64
    __shared__ float s_b1[64], s_w2[64 * 3], s_b2[3];
    int tid = threadIdx.x;
    int n0 = blockIdx.x * 128;

    for (int i = tid; i < 4096; i += 128) s_w1[i] = w1[i];
    if (tid < 64) s_b1[tid] = b1[tid];
    for (int i = tid; i < 192; i += 128) s_w2[i] = w2[i];
    if (tid < 3) s_b2[tid] = b2[tid];
    for (int i = tid; i < 128 * 64; i += 128) {
        int r = i >> 6, k = i & 63;
        int n = n0 + r;
        s_h[r * 65 + k] = (n < N) ? g_h[(size_t)n * 64 + k] : 0.f;
    }
    __syncthreads();

    int n = n0 + tid;
    if (n >= N) return;

    float hrow[64];
#pragma unroll
    for (int k = 0; k < 64; k++) hrow[k] = s_h[tid * 65 + k];

    float hid[64];
#pragma unroll 4
    for (int j = 0; j < 64; j++) {
        float acc = s_b1[j];
#pragma unroll
        for (int k = 0; k < 64; k++) acc = fmaf(hrow[k], s_w1[k * 64 + j], acc);
        hid[j] = fmaxf(acc, 0.f);
    }
#pragma unroll
    for (int c = 0; c < 3; c++) {
        float acc = s_b2[c];
#pragma unroll
        for (int k = 0; k < 64; k++) acc = fmaf(hid[k], s_w2[k * 3 + c], acc);
        out[(size_t)n * 3 + c] = 6.283185307179586f / (1.f + expf(-acc));
    }
}

// ---------------------------------------------------------------------------
extern "C" void kernel_launch(void* const* d_in, const int* in_sizes, int n_in,
                              void* d_out, int out_size)
{
    const float* x      = (const float*)d_in[0];
    const int*   ei     = (const int*)  d_in[1];
    const float* enc_w1 = (const float*)d_in[2];
    const float* enc_b1 = (const float*)d_in[3];
    const float* enc_w2 = (const float*)d_in[4];
    const float* enc_b2 = (const float*)d_in[5];
    const float* msg_w1 = (const float*)d_in[6];
    const float* msg_b1 = (const float*)d_in[7];
    const float* msg_w2 = (const float*)d_in[8];
    const float* msg_b2 = (const float*)d_in[9];
    const float* upd_w1 = (const float*)d_in[10];
    const float* upd_b1 = (const float*)d_in[11];
    const float* upd_w2 = (const float*)d_in[12];
    const float* upd_b2 = (const float*)d_in[13];
    const float* out_w1 = (const float*)d_in[14];
    const float* out_b1 = (const float*)d_in[15];
    const float* out_w2 = (const float*)d_in[16];
    const float* out_b2 = (const float*)d_in[17];

    int N = in_sizes[0] / 5;
    int E = in_sizes[1] / 2;
    if (N > NMAX) N = NMAX;
    if (E > EMAX) E = EMAX;
    const int* src = ei;
    const int* dstp = ei + E;

    const int ENC_SM = (128 * 65 + 64 * 64) * 4;    // 49664
    const int PRE_SM = (128 * 65 + 64 * 128) * 4;   // 66048
    const int EDG_SM = (128 * HS + 64 * WS) * 4;    // 53248
    const int UPD_SM = (128 * 129 + 128 * 64) * 4;  // 98816
    const int OUT_SM = (128 * 65 + 64 * 64) * 4;    // 49664
    cudaFuncSetAttribute(k_encoder, cudaFuncAttributeMaxDynamicSharedMemorySize, ENC_SM);
    cudaFuncSetAttribute(k_pre,  cudaFuncAttributeMaxDynamicSharedMemorySize, PRE_SM);
    cudaFuncSetAttribute(k_edge, cudaFuncAttributeMaxDynamicSharedMemorySize, EDG_SM);
    cudaFuncSetAttribute(k_upd,  cudaFuncAttributeMaxDynamicSharedMemorySize, UPD_SM);
    cudaFuncSetAttribute(k_out,  cudaFuncAttributeMaxDynamicSharedMemorySize, OUT_SM);

    int nbN256 = (N + 255) / 256;
    int nbE256 = (E + 255) / 256;
    int nbN128 = (N + 127) / 128;
    int nbE128 = (E + 127) / 128;

    k_zero_cnt<<<nbN256, 256>>>(N);
    k_count<<<nbE256, 256>>>(dstp, E);
    k_inv<<<nbN256, 256>>>(N);
    k_encoder<<<nbN128, 256, ENC_SM>>>(x, enc_w1, enc_b1, enc_w2, enc_b2, N);

    for (int l = 0; l < 3; l++) {
        k_pre<<<nbN128, 256, PRE_SM>>>(msg_w1 + l * 128 * 64, N);
        k_edge<<<nbE128, 256, EDG_SM>>>(src, dstp,
                                        msg_b1 + l * 64,
                                        msg_w2 + l * 64 * 64,
                                        msg_b2 + l * 64, E);
        k_upd<<<nbN128, 256, UPD_SM>>>(upd_w1 + l * 128 * 64,
                                       upd_b1 + l * 64,
                                       upd_w2 + l * 64 * 64,
                                       upd_b2 + l * 64, N);
    }

    k_out<<<nbN128, 128, OUT_SM>>>(out_w1, out_b1, out_w2, out_b2,
                                   (float*)d_out, N);
}

// round 7
// speedup vs baseline: 1.8497x; 1.3904x over previous
#include <cuda_runtime.h>

// ---------------------------------------------------------------------------
// FixedSimpleGNN: 3-layer MPNN, N=100000, E=1000000, H=64.
//
//   a_s = h @ W1_top, a_d = h @ W1_bot per NODE (factorized concat GEMM, mma)
//   per edge: hidden = relu(a_s[src]+a_d[dst]+b1)     (float4 gather)
//             m      = relu(hidden @ W2 + b2)          (tf32 mma.sync)
//             agg[dst] += m                            (float4 atomics)
//   update: h = mlp2(concat(h, agg/deg))               (tf32 mma.sync)
// ---------------------------------------------------------------------------

#define NMAX 100000
#define EMAX 1000000
#define HS 68    // smem row stride (floats): 4*qrow+qcol bank pattern, conflict-free
#define US 132   // k_upd phase-1 stride (128 + 4)

typedef unsigned int uint;

__device__ float g_h  [NMAX * 64];
__device__ float g_as [NMAX * 64];
__device__ float g_ad [NMAX * 64];
__device__ float g_agg[NMAX * 64];
__device__ float g_cnt[NMAX];
__device__ float g_inv[NMAX];

__device__ __forceinline__ float to_tf32(float x) {
    uint u;
    asm("cvt.rna.tf32.f32 %0, %1;" : "=r"(u) : "f"(x));
    return __uint_as_float(u);
}
__device__ __forceinline__ uint to_tf32u(float x) {
    uint u;
    asm("cvt.rna.tf32.f32 %0, %1;" : "=r"(u) : "f"(x));
    return u;
}
__device__ __forceinline__ void mma_tf32(
    float& c0, float& c1, float& c2, float& c3,
    uint a0, uint a1, uint a2, uint a3, uint b0, uint b1)
{
    asm volatile(
        "mma.sync.aligned.m16n8k8.row.col.f32.tf32.tf32.f32 "
        "{%0,%1,%2,%3}, {%4,%5,%6,%7}, {%8,%9}, {%0,%1,%2,%3};"
        : "+f"(c0), "+f"(c1), "+f"(c2), "+f"(c3)
        : "r"(a0), "r"(a1), "r"(a2), "r"(a3), "r"(b0), "r"(b1));
}

// ---------------------------------------------------------------------------
__global__ void k_zero_cnt(int N) {
    int i = blockIdx.x * blockDim.x + threadIdx.x;
    if (i < N) g_cnt[i] = 0.f;
}
__global__ void k_count(const int* __restrict__ dst, int E) {
    int e = blockIdx.x * blockDim.x + threadIdx.x;
    if (e < E) atomicAdd(&g_cnt[dst[e]], 1.f);
}
__global__ void k_inv(int N) {
    int i = blockIdx.x * blockDim.x + threadIdx.x;
    if (i < N) g_inv[i] = 1.f / fmaxf(g_cnt[i], 1.f);
}

// ---------------------------------------------------------------------------
// encoder (scalar tiled; small): h = relu(relu(x@w1+b1)@w2+b2), x [N,5]
// ---------------------------------------------------------------------------
__global__ __launch_bounds__(256) void k_encoder(
    const float* __restrict__ x,
    const float* __restrict__ w1, const float* __restrict__ b1,
    const float* __restrict__ w2, const float* __restrict__ b2, int N)
{
    extern __shared__ float sm[];
    float* s_hid = sm;             // 128 * 65
    float* s_w2  = sm + 128 * 65;  // 64 * 64
    __shared__ float s_w1[5 * 64], s_b1[64], s_b2[64];
    __shared__ float s_x[128 * 6];
    int tid = threadIdx.x;
    int n0 = blockIdx.x * 128;

    for (int i = tid; i < 5 * 64; i += 256)  s_w1[i] = w1[i];
    for (int i = tid; i < 64 * 64; i += 256) s_w2[i] = w2[i];
    if (tid < 64) { s_b1[tid] = b1[tid]; s_b2[tid] = b2[tid]; }
    for (int i = tid; i < 128 * 5; i += 256) {
        int r = i / 5, k = i % 5;
        int n = n0 + r;
        s_x[r * 6 + k] = (n < N) ? x[(size_t)n * 5 + k] : 0.f;
    }
    __syncthreads();

    int r0 = (tid >> 4) * 8;
    int c0 = (tid & 15) * 4;

    float acc[8][4];
#pragma unroll
    for (int r = 0; r < 8; r++)
#pragma unroll
        for (int c = 0; c < 4; c++) acc[r][c] = 0.f;
#pragma unroll
    for (int k = 0; k < 5; k++) {
        float4 b = *(const float4*)(s_w1 + k * 64 + c0);
#pragma unroll
        for (int r = 0; r < 8; r++) {
            float a = s_x[(r0 + r) * 6 + k];
            acc[r][0] = fmaf(a, b.x, acc[r][0]);
            acc[r][1] = fmaf(a, b.y, acc[r][1]);
            acc[r][2] = fmaf(a, b.z, acc[r][2]);
            acc[r][3] = fmaf(a, b.w, acc[r][3]);
        }
    }
#pragma unroll
    for (int r = 0; r < 8; r++)
#pragma unroll
        for (int c = 0; c < 4; c++)
            s_hid[(r0 + r) * 65 + c0 + c] = fmaxf(acc[r][c] + s_b1[c0 + c], 0.f);
    __syncthreads();

    float acc2[8][4];
#pragma unroll
    for (int r = 0; r < 8; r++)
#pragma unroll
        for (int c = 0; c < 4; c++) acc2[r][c] = 0.f;
#pragma unroll 4
    for (int k = 0; k < 64; k++) {
        float4 b = *(const float4*)(s_w2 + k * 64 + c0);
#pragma unroll
        for (int r = 0; r < 8; r++) {
            float a = s_hid[(r0 + r) * 65 + k];
            acc2[r][0] = fmaf(a, b.x, acc2[r][0]);
            acc2[r][1] = fmaf(a, b.y, acc2[r][1]);
            acc2[r][2] = fmaf(a, b.z, acc2[r][2]);
            acc2[r][3] = fmaf(a, b.w, acc2[r][3]);
        }
    }
#pragma unroll
    for (int r = 0; r < 8; r++) {
        int n = n0 + r0 + r;
        if (n >= N) break;
        float4 v;
        v.x = fmaxf(acc2[r][0] + s_b2[c0 + 0], 0.f);
        v.y = fmaxf(acc2[r][1] + s_b2[c0 + 1], 0.f);
        v.z = fmaxf(acc2[r][2] + s_b2[c0 + 2], 0.f);
        v.w = fmaxf(acc2[r][3] + s_b2[c0 + 3], 0.f);
        *(float4*)(g_h + (size_t)n * 64 + c0) = v;
    }
}

// ---------------------------------------------------------------------------
// k_pre (mma): [a_s | a_d] = h @ W' (W'[k][j<64]=w1[k][j], W'[k][j>=64]=w1[64+k][j-64])
// 256 threads, 128 nodes/block; warp = 16 rows x 128 cols, K=64. Zeroes g_agg.
// ---------------------------------------------------------------------------
__global__ __launch_bounds__(256) void k_pre(const float* __restrict__ w1, int N)
{
    __shared__ float s_h[128 * HS];
    int tid = threadIdx.x;
    int n0 = blockIdx.x * 128;

    // stage h rows as tf32 (float4 loads) + zero g_agg
#pragma unroll
    for (int i = 0; i < 8; i++) {
        int lin = i * 256 + tid;
        int r = lin >> 4, q = lin & 15;
        int n = n0 + r;
        float4 v = make_float4(0.f, 0.f, 0.f, 0.f);
        if (n < N) {
            float4 a = __ldg((const float4*)(g_h + (size_t)n * 64 + q * 4));
            v.x = to_tf32(a.x); v.y = to_tf32(a.y);
            v.z = to_tf32(a.z); v.w = to_tf32(a.w);
            *(float4*)(g_agg + (size_t)n * 64 + q * 4) = make_float4(0.f, 0.f, 0.f, 0.f);
        }
        *(float4*)(s_h + r * HS + q * 4) = v;
    }
    __syncthreads();

    int warp = tid >> 5, lane = tid & 31;
    int m0 = warp * 16;
    int qrow = lane >> 2, qcol = lane & 3;

    float acc[16][4];
#pragma unroll
    for (int nt = 0; nt < 16; nt++)
#pragma unroll
        for (int c = 0; c < 4; c++) acc[nt][c] = 0.f;

    // per-nt column base pointers into w1 (top/bottom half select)
    const float* colb[16];
#pragma unroll
    for (int nt = 0; nt < 16; nt++) {
        int col = nt * 8 + qrow;
        colb[nt] = (col < 64) ? (w1 + col) : (w1 + 64 * 64 + (col - 64));
    }

    const float* Ab = s_h + (m0 + qrow) * HS + qcol;
#pragma unroll
    for (int kt = 0; kt < 8; kt++) {
        uint a0 = __float_as_uint(Ab[kt * 8]);
        uint a1 = __float_as_uint(Ab[kt * 8 + 8 * HS]);
        uint a2 = __float_as_uint(Ab[kt * 8 + 4]);
        uint a3 = __float_as_uint(Ab[kt * 8 + 4 + 8 * HS]);
        int k0 = (kt * 8 + qcol) * 64;
#pragma unroll
        for (int nt = 0; nt < 16; nt++) {
            uint b0 = to_tf32u(__ldg(colb[nt] + k0));
            uint b1v = to_tf32u(__ldg(colb[nt] + k0 + 4 * 64));
            mma_tf32(acc[nt][0], acc[nt][1], acc[nt][2], acc[nt][3],
                     a0, a1, a2, a3, b0, b1v);
        }
    }

    // write out: rows m0+qrow, m0+qrow+8; cols nt*8+qcol*2 (+1)
#pragma unroll
    for (int nt = 0; nt < 16; nt++) {
        int col = nt * 8 + qcol * 2;
        float* base = (col < 64) ? g_as : g_ad;
        int c = (col < 64) ? col : col - 64;
        int nA = n0 + m0 + qrow;
        int nB = nA + 8;
        if (nA < N) *(float2*)(base + (size_t)nA * 64 + c) = make_float2(acc[nt][0], acc[nt][1]);
        if (nB < N) *(float2*)(base + (size_t)nB * 64 + c) = make_float2(acc[nt][2], acc[nt][3]);
    }
}

// ---------------------------------------------------------------------------
// k_edge (mma v3): 256 threads, 128 edges/block.
//   float4 gather -> s_hid (tf32), mma with W2 B-frags direct from global,
//   epilogue -> s_hid, float4 atomic scatter.
// ---------------------------------------------------------------------------
__global__ __launch_bounds__(256) void k_edge(
    const int* __restrict__ src, const int* __restrict__ dst,
    const float* __restrict__ b1, const float* __restrict__ w2,
    const float* __restrict__ b2, int E)
{
    __shared__ float s_hid[128 * HS];
    __shared__ float s_b1[64], s_b2[64];
    __shared__ int s_src[128], s_dst[128];
    int tid = threadIdx.x;
    int e0 = blockIdx.x * 128;

    if (tid < 64) { s_b1[tid] = b1[tid]; s_b2[tid] = b2[tid]; }
    if (tid >= 128 && tid < 256) {
        int t = tid - 128;
        int e = e0 + t;
        bool v = (e < E);
        s_src[t] = v ? src[e] : -1;
        s_dst[t] = v ? dst[e] : -1;
    }
    __syncthreads();

    // gather + first layer: 128 edges x 16 float4 quarters
#pragma unroll
    for (int i = 0; i < 8; i++) {
        int lin = i * 256 + tid;
        int e = lin >> 4, q = lin & 15;
        int s = s_src[e];
        float4 v = make_float4(0.f, 0.f, 0.f, 0.f);
        if (s >= 0) {
            int d = s_dst[e];
            float4 a = __ldg((const float4*)(g_as + (size_t)s * 64 + q * 4));
            float4 b = __ldg((const float4*)(g_ad + (size_t)d * 64 + q * 4));
            float4 bb = *(const float4*)(s_b1 + q * 4);
            v.x = to_tf32(fmaxf(a.x + b.x + bb.x, 0.f));
            v.y = to_tf32(fmaxf(a.y + b.y + bb.y, 0.f));
            v.z = to_tf32(fmaxf(a.z + b.z + bb.z, 0.f));
            v.w = to_tf32(fmaxf(a.w + b.w + bb.w, 0.f));
        }
        *(float4*)(s_hid + e * HS + q * 4) = v;
    }
    __syncthreads();

    int warp = tid >> 5, lane = tid & 31;
    int m0 = warp * 16;
    int qrow = lane >> 2, qcol = lane & 3;

    float acc[8][4];
#pragma unroll
    for (int nt = 0; nt < 8; nt++)
#pragma unroll
        for (int c = 0; c < 4; c++) acc[nt][c] = 0.f;

    const float* Ab = s_hid + (m0 + qrow) * HS + qcol;
    const float* Bb = w2 + qcol * 64 + qrow;   // w2[k][n] row-major

#pragma unroll
    for (int kt = 0; kt < 8; kt++) {
        uint a0 = __float_as_uint(Ab[kt * 8]);
        uint a1 = __float_as_uint(Ab[kt * 8 + 8 * HS]);
        uint a2 = __float_as_uint(Ab[kt * 8 + 4]);
        uint a3 = __float_as_uint(Ab[kt * 8 + 4 + 8 * HS]);
        const float* Bk = Bb + kt * 8 * 64;
#pragma unroll
        for (int nt = 0; nt < 8; nt++) {
            uint b0 = to_tf32u(__ldg(Bk + nt * 8));
            uint b1v = to_tf32u(__ldg(Bk + nt * 8 + 4 * 64));
            mma_tf32(acc[nt][0], acc[nt][1], acc[nt][2], acc[nt][3],
                     a0, a1, a2, a3, b0, b1v);
        }
    }
    __syncthreads();

    // epilogue: bias + relu -> s_hid
#pragma unroll
    for (int nt = 0; nt < 8; nt++) {
        int c = nt * 8 + qcol * 2;
        float bx = s_b2[c], by = s_b2[c + 1];
        float2 lo, hi;
        lo.x = fmaxf(acc[nt][0] + bx, 0.f);
        lo.y = fmaxf(acc[nt][1] + by, 0.f);
        hi.x = fmaxf(acc[nt][2] + bx, 0.f);
        hi.y = fmaxf(acc[nt][3] + by, 0.f);
        *(float2*)(s_hid + (m0 + qrow) * HS + c)     = lo;
        *(float2*)(s_hid + (m0 + qrow + 8) * HS + c) = hi;
    }
    __syncthreads();

    // scatter: 128 edges x 16 float4
#pragma unroll
    for (int i = 0; i < 8; i++) {
        int lin = i * 256 + tid;
        int e = lin >> 4, q = lin & 15;
        int d = s_dst[e];
        if (d >= 0) {
            float4 v = *(const float4*)(s_hid + e * HS + q * 4);
            atomicAdd((float4*)(g_agg + (size_t)d * 64 + q * 4), v);
        }
    }
}

// ---------------------------------------------------------------------------
// k_upd (mma): h = mlp2(concat(h, agg*inv), w1, b1, w2, b2) in place.
// 256 threads, 128 nodes/block; phase1 K=128 (stride US), phase2 K=64 (HS).
// ---------------------------------------------------------------------------
__global__ __launch_bounds__(256) void k_upd(
    const float* __restrict__ w1, const float* __restrict__ b1,
    const float* __restrict__ w2, const float* __restrict__ b2, int N)
{
    extern __shared__ float s_in[];   // 128 * US floats
    __shared__ float s_b1[64], s_b2[64];
    int tid = threadIdx.x;
    int n0 = blockIdx.x * 128;

    if (tid < 64) { s_b1[tid] = b1[tid]; s_b2[tid] = b2[tid]; }

    // stage concat(h, agg*inv) as tf32: 128 rows x 32 float4 quarters
#pragma unroll
    for (int i = 0; i < 16; i++) {
        int lin = i * 256 + tid;
        int r = lin >> 5, kq = lin & 31;
        int n = n0 + r;
        float4 v = make_float4(0.f, 0.f, 0.f, 0.f);
        if (n < N) {
            if (kq < 16) {
                float4 a = __ldg((const float4*)(g_h + (size_t)n * 64 + kq * 4));
                v.x = to_tf32(a.x); v.y = to_tf32(a.y);
                v.z = to_tf32(a.z); v.w = to_tf32(a.w);
            } else {
                float iv = __ldg(g_inv + n);
                float4 a = __ldg((const float4*)(g_agg + (size_t)n * 64 + (kq - 16) * 4));
                v.x = to_tf32(a.x * iv); v.y = to_tf32(a.y * iv);
                v.z = to_tf32(a.z * iv); v.w = to_tf32(a.w * iv);
            }
        }
        *(float4*)(s_in + r * US + kq * 4) = v;
    }
    __syncthreads();

    int warp = tid >> 5, lane = tid & 31;
    int m0 = warp * 16;
    int qrow = lane >> 2, qcol = lane & 3;

    // phase 1: [128 x 128] @ w1[128,64]
    float acc[8][4];
#pragma unroll
    for (int nt = 0; nt < 8; nt++)
#pragma unroll
        for (int c = 0; c < 4; c++) acc[nt][c] = 0.f;

    {
        const float* Ab = s_in + (m0 + qrow) * US + qcol;
        const float* Bb = w1 + qcol * 64 + qrow;
#pragma unroll
        for (int kt = 0; kt < 16; kt++) {
            uint a0 = __float_as_uint(Ab[kt * 8]);
            uint a1 = __float_as_uint(Ab[kt * 8 + 8 * US]);
            uint a2 = __float_as_uint(Ab[kt * 8 + 4]);
            uint a3 = __float_as_uint(Ab[kt * 8 + 4 + 8 * US]);
            const float* Bk = Bb + kt * 8 * 64;
#pragma unroll
            for (int nt = 0; nt < 8; nt++) {
                uint b0 = to_tf32u(__ldg(Bk + nt * 8));
                uint b1v = to_tf32u(__ldg(Bk + nt * 8 + 4 * 64));
                mma_tf32(acc[nt][0], acc[nt][1], acc[nt][2], acc[nt][3],
                         a0, a1, a2, a3, b0, b1v);
            }
        }
    }
    __syncthreads();   // done reading stride-US data

    // hidden = relu(acc + b1) -> s_in (stride HS, tf32)
#pragma unroll
    for (int nt = 0; nt < 8; nt++) {
        int c = nt * 8 + qcol * 2;
        float bx = s_b1[c], by = s_b1[c + 1];
        float2 lo, hi;
        lo.x = to_tf32(fmaxf(acc[nt][0] + bx, 0.f));
        lo.y = to_tf32(fmaxf(acc[nt][1] + by, 0.f));
        hi.x = to_tf32(fmaxf(acc[nt][2] + bx, 0.f));
        hi.y = to_tf32(fmaxf(acc[nt][3] + by, 0.f));
        *(float2*)(s_in + (m0 + qrow) * HS + c)     = lo;
        *(float2*)(s_in + (m0 + qrow + 8) * HS + c) = hi;
    }
    __syncthreads();

    // phase 2: [128 x 64] @ w2[64,64]
    float acc2[8][4];
#pragma unroll
    for (int nt = 0; nt < 8; nt++)
#pragma unroll
        for (int c = 0; c < 4; c++) acc2[nt][c] = 0.f;

    {
        const float* Ab = s_in + (m0 + qrow) * HS + qcol;
        const float* Bb = w2 + qcol * 64 + qrow;
#pragma unroll
        for (int kt = 0; kt < 8; kt++) {
            uint a0 = __float_as_uint(Ab[kt * 8]);
            uint a1 = __float_as_uint(Ab[kt * 8 + 8 * HS]);
            uint a2 = __float_as_uint(Ab[kt * 8 + 4]);
            uint a3 = __float_as_uint(Ab[kt * 8 + 4 + 8 * HS]);
            const float* Bk = Bb + kt * 8 * 64;
#pragma unroll
            for (int nt = 0; nt < 8; nt++) {
                uint b0 = to_tf32u(__ldg(Bk + nt * 8));
                uint b1v = to_tf32u(__ldg(Bk + nt * 8 + 4 * 64));
                mma_tf32(acc2[nt][0], acc2[nt][1], acc2[nt][2], acc2[nt][3],
                         a0, a1, a2, a3, b0, b1v);
            }
        }
    }

    // h = relu(acc2 + b2) -> g_h
#pragma unroll
    for (int nt = 0; nt < 8; nt++) {
        int c = nt * 8 + qcol * 2;
        float bx = s_b2[c], by = s_b2[c + 1];
        int nA = n0 + m0 + qrow;
        int nB = nA + 8;
        if (nA < N) {
            float2 v;
            v.x = fmaxf(acc2[nt][0] + bx, 0.f);
            v.y = fmaxf(acc2[nt][1] + by, 0.f);
            *(float2*)(g_h + (size_t)nA * 64 + c) = v;
        }
        if (nB < N) {
            float2 v;
            v.x = fmaxf(acc2[nt][2] + bx, 0.f);
            v.y = fmaxf(acc2[nt][3] + by, 0.f);
            *(float2*)(g_h + (size_t)nB * 64 + c) = v;
        }
    }
}

// ---------------------------------------------------------------------------
// k_out: pred = relu(h@ow1+ob1)@ow2+ob2; out = 2*pi*sigmoid(pred), [N,3]
// ---------------------------------------------------------------------------
__global__ __launch_bounds__(128) void k_out(
    const float* __restrict__ w1, const float* __restrict__ b1,
    const float* __restrict__ w2, const float* __restrict__ b2,
    float* __restrict__ out, int N)
{
    extern __shared__ float sm[];
    float* s_h  = sm;             // 128 * 65
    float* s_w1 = sm + 128 * 65;  // 64 * 64
    __shared__ float s_b1[64], s_w2[64 * 3], s_b2[3];
    int tid = threadIdx.x;
    int n0 = blockIdx.x * 128;

    for (int i = tid; i < 4096; i += 128) s_w1[i] = w1[i];
    if (tid < 64) s_b1[tid] = b1[tid];
    for (int i = tid; i < 192; i += 128) s_w2[i] = w2[i];
    if (tid < 3) s_b2[tid] = b2[tid];
    for (int i = tid; i < 128 * 64; i += 128) {
        int r = i >> 6, k = i & 63;
        int n = n0 + r;
        s_h[r * 65 + k] = (n < N) ? g_h[(size_t)n * 64 + k] : 0.f;
    }
    __syncthreads();

    int n = n0 + tid;
    if (n >= N) return;

    float hrow[64];
#pragma unroll
    for (int k = 0; k < 64; k++) hrow[k] = s_h[tid * 65 + k];

    float hid[64];
#pragma unroll 4
    for (int j = 0; j < 64; j++) {
        float acc = s_b1[j];
#pragma unroll
        for (int k = 0; k < 64; k++) acc = fmaf(hrow[k], s_w1[k * 64 + j], acc);
        hid[j] = fmaxf(acc, 0.f);
    }
#pragma unroll
    for (int c = 0; c < 3; c++) {
        float acc = s_b2[c];
#pragma unroll
        for (int k = 0; k < 64; k++) acc = fmaf(hid[k], s_w2[k * 3 + c], acc);
        out[(size_t)n * 3 + c] = 6.283185307179586f / (1.f + expf(-acc));
    }
}

// ---------------------------------------------------------------------------
extern "C" void kernel_launch(void* const* d_in, const int* in_sizes, int n_in,
                              void* d_out, int out_size)
{
    const float* x      = (const float*)d_in[0];
    const int*   ei     = (const int*)  d_in[1];
    const float* enc_w1 = (const float*)d_in[2];
    const float* enc_b1 = (const float*)d_in[3];
    const float* enc_w2 = (const float*)d_in[4];
    const float* enc_b2 = (const float*)d_in[5];
    const float* msg_w1 = (const float*)d_in[6];
    const float* msg_b1 = (const float*)d_in[7];
    const float* msg_w2 = (const float*)d_in[8];
    const float* msg_b2 = (const float*)d_in[9];
    const float* upd_w1 = (const float*)d_in[10];
    const float* upd_b1 = (const float*)d_in[11];
    const float* upd_w2 = (const float*)d_in[12];
    const float* upd_b2 = (const float*)d_in[13];
    const float* out_w1 = (const float*)d_in[14];
    const float* out_b1 = (const float*)d_in[15];
    const float* out_w2 = (const float*)d_in[16];
    const float* out_b2 = (const float*)d_in[17];

    int N = in_sizes[0] / 5;
    int E = in_sizes[1] / 2;
    if (N > NMAX) N = NMAX;
    if (E > EMAX) E = EMAX;
    const int* src = ei;
    const int* dstp = ei + E;

    const int ENC_SM = (128 * 65 + 64 * 64) * 4;    // 49664
    const int UPD_SM = 128 * US * 4;                // 67584
    const int OUT_SM = (128 * 65 + 64 * 64) * 4;    // 49664
    cudaFuncSetAttribute(k_encoder, cudaFuncAttributeMaxDynamicSharedMemorySize, ENC_SM);
    cudaFuncSetAttribute(k_upd,  cudaFuncAttributeMaxDynamicSharedMemorySize, UPD_SM);
    cudaFuncSetAttribute(k_out,  cudaFuncAttributeMaxDynamicSharedMemorySize, OUT_SM);

    int nbN256 = (N + 255) / 256;
    int nbE256 = (E + 255) / 256;
    int nbN128 = (N + 127) / 128;
    int nbE128 = (E + 127) / 128;

    k_zero_cnt<<<nbN256, 256>>>(N);
    k_count<<<nbE256, 256>>>(dstp, E);
    k_inv<<<nbN256, 256>>>(N);
    k_encoder<<<nbN128, 256, ENC_SM>>>(x, enc_w1, enc_b1, enc_w2, enc_b2, N);

    for (int l = 0; l < 3; l++) {
        k_pre<<<nbN128, 256>>>(msg_w1 + l * 128 * 64, N);
        k_edge<<<nbE128, 256>>>(src, dstp,
                                msg_b1 + l * 64,
                                msg_w2 + l * 64 * 64,
                                msg_b2 + l * 64, E);
        k_upd<<<nbN128, 256, UPD_SM>>>(upd_w1 + l * 128 * 64,
                                       upd_b1 + l * 64,
                                       upd_w2 + l * 64 * 64,
                                       upd_b2 + l * 64, N);
    }

    k_out<<<nbN128, 128, OUT_SM>>>(out_w1, out_b1, out_w2, out_b2,
                                   (float*)d_out, N);
}

// round 8
// speedup vs baseline: 2.7151x; 1.4679x over previous
#include <cuda_runtime.h>
#include <cuda_bf16.h>

// ---------------------------------------------------------------------------
// FixedSimpleGNN: 3-layer MPNN, N=100000, E=1000000, H=64.
//   Factorized message layer-1 (per-node a_s/a_d, stored bf16x2),
//   per-edge bf16 mma.m16n8k16 for layer-2, float4 atomic scatter,
//   bf16 mma update MLP. Weights pre-packed into B-fragment bf16x2 layout.
// ---------------------------------------------------------------------------

#define NMAX 100000
#define EMAX 1000000

typedef unsigned int uint;

// scratch (static device memory)
__device__ float g_h  [NMAX * 64];
__device__ uint  g_as [NMAX * 32];   // bf16x2 pairs
__device__ uint  g_ad [NMAX * 32];   // bf16x2 pairs
__device__ float g_agg[NMAX * 64];
__device__ float g_cnt[NMAX];
__device__ float g_inv[NMAX];

// packed bf16x2 weights, per layer (12288 uints each):
//   [0,4096):      msg W' pairs  [32][128]  (W'[k][j<64]=w1[k][j]; [j>=64]=w1[64+k][j-64])
//   [4096,6144):   msg w2 pairs  [32][64]
//   [6144,10240):  upd w1 pairs  [64][64]
//   [10240,12288): upd w2 pairs  [32][64]
__device__ uint p_w[3 * 12288];

__device__ __forceinline__ uint bpack(float lo, float hi) {
    __nv_bfloat162 p = __floats2bfloat162_rn(lo, hi);
    return *(uint*)&p;
}
__device__ __forceinline__ uint badd2(uint a, uint b) {
    __nv_bfloat162 r = __hadd2(*(__nv_bfloat162*)&a, *(__nv_bfloat162*)&b);
    return *(uint*)&r;
}
__device__ __forceinline__ uint brelu2(uint a) {
    __nv_bfloat162 z = __float2bfloat162_rn(0.f);
    __nv_bfloat162 r = __hmax2(*(__nv_bfloat162*)&a, z);
    return *(uint*)&r;
}
__device__ __forceinline__ void mma_bf16(
    float& c0, float& c1, float& c2, float& c3,
    uint a0, uint a1, uint a2, uint a3, uint b0, uint b1)
{
    asm volatile(
        "mma.sync.aligned.m16n8k16.row.col.f32.bf16.bf16.f32 "
        "{%0,%1,%2,%3}, {%4,%5,%6,%7}, {%8,%9}, {%0,%1,%2,%3};"
        : "+f"(c0), "+f"(c1), "+f"(c2), "+f"(c3)
        : "r"(a0), "r"(a1), "r"(a2), "r"(a3), "r"(b0), "r"(b1));
}

// ---------------------------------------------------------------------------
// k_pack: build bf16x2 B-fragment weight arrays (runs once per call, tiny)
// ---------------------------------------------------------------------------
__global__ void k_pack(const float* __restrict__ msg_w1,
                       const float* __restrict__ msg_w2,
                       const float* __restrict__ upd_w1,
                       const float* __restrict__ upd_w2)
{
    int idx = blockIdx.x * blockDim.x + threadIdx.x;
    if (idx >= 3 * 12288) return;
    int l = idx / 12288, r = idx % 12288;
    const float* mw1 = msg_w1 + l * 8192;
    const float* mw2 = msg_w2 + l * 4096;
    const float* uw1 = upd_w1 + l * 8192;
    const float* uw2 = upd_w2 + l * 4096;
    float lo, hi;
    if (r < 4096) {
        int kk = r >> 7, j = r & 127;
        if (j < 64) { lo = mw1[(2*kk)*64 + j];          hi = mw1[(2*kk+1)*64 + j]; }
        else        { lo = mw1[(64+2*kk)*64 + (j-64)];  hi = mw1[(64+2*kk+1)*64 + (j-64)]; }
    } else if (r < 6144) {
        int t = r - 4096; int kk = t >> 6, n = t & 63;
        lo = mw2[2*kk*64 + n]; hi = mw2[(2*kk+1)*64 + n];
    } else if (r < 10240) {
        int t = r - 6144; int kk = t >> 6, n = t & 63;
        lo = uw1[2*kk*64 + n]; hi = uw1[(2*kk+1)*64 + n];
    } else {
        int t = r - 10240; int kk = t >> 6, n = t & 63;
        lo = uw2[2*kk*64 + n]; hi = uw2[(2*kk+1)*64 + n];
    }
    p_w[idx] = bpack(lo, hi);
}

// ---------------------------------------------------------------------------
__global__ void k_zero_cnt(int N) {
    int i = blockIdx.x * blockDim.x + threadIdx.x;
    if (i < N) g_cnt[i] = 0.f;
}
__global__ void k_count(const int* __restrict__ dst, int E) {
    int e = blockIdx.x * blockDim.x + threadIdx.x;
    if (e < E) atomicAdd(&g_cnt[dst[e]], 1.f);
}
__global__ void k_inv(int N) {
    int i = blockIdx.x * blockDim.x + threadIdx.x;
    if (i < N) g_inv[i] = 1.f / fmaxf(g_cnt[i], 1.f);
}

// ---------------------------------------------------------------------------
// encoder (scalar tiled): h = relu(relu(x@w1+b1)@w2+b2), x [N,5]
// ---------------------------------------------------------------------------
__global__ __launch_bounds__(256) void k_encoder(
    const float* __restrict__ x,
    const float* __restrict__ w1, const float* __restrict__ b1,
    const float* __restrict__ w2, const float* __restrict__ b2, int N)
{
    extern __shared__ float sm[];
    float* s_hid = sm;             // 128 * 65
    float* s_w2  = sm + 128 * 65;  // 64 * 64
    __shared__ float s_w1[5 * 64], s_b1[64], s_b2[64];
    __shared__ float s_x[128 * 6];
    int tid = threadIdx.x;
    int n0 = blockIdx.x * 128;

    for (int i = tid; i < 5 * 64; i += 256)  s_w1[i] = w1[i];
    for (int i = tid; i < 64 * 64; i += 256) s_w2[i] = w2[i];
    if (tid < 64) { s_b1[tid] = b1[tid]; s_b2[tid] = b2[tid]; }
    for (int i = tid; i < 128 * 5; i += 256) {
        int r = i / 5, k = i % 5;
        int n = n0 + r;
        s_x[r * 6 + k] = (n < N) ? x[(size_t)n * 5 + k] : 0.f;
    }
    __syncthreads();

    int r0 = (tid >> 4) * 8;
    int c0 = (tid & 15) * 4;

    float acc[8][4];
#pragma unroll
    for (int r = 0; r < 8; r++)
#pragma unroll
        for (int c = 0; c < 4; c++) acc[r][c] = 0.f;
#pragma unroll
    for (int k = 0; k < 5; k++) {
        float4 b = *(const float4*)(s_w1 + k * 64 + c0);
#pragma unroll
        for (int r = 0; r < 8; r++) {
            float a = s_x[(r0 + r) * 6 + k];
            acc[r][0] = fmaf(a, b.x, acc[r][0]);
            acc[r][1] = fmaf(a, b.y, acc[r][1]);
            acc[r][2] = fmaf(a, b.z, acc[r][2]);
            acc[r][3] = fmaf(a, b.w, acc[r][3]);
        }
    }
#pragma unroll
    for (int r = 0; r < 8; r++)
#pragma unroll
        for (int c = 0; c < 4; c++)
            s_hid[(r0 + r) * 65 + c0 + c] = fmaxf(acc[r][c] + s_b1[c0 + c], 0.f);
    __syncthreads();

    float acc2[8][4];
#pragma unroll
    for (int r = 0; r < 8; r++)
#pragma unroll
        for (int c = 0; c < 4; c++) acc2[r][c] = 0.f;
#pragma unroll 4
    for (int k = 0; k < 64; k++) {
        float4 b = *(const float4*)(s_w2 + k * 64 + c0);
#pragma unroll
        for (int r = 0; r < 8; r++) {
            float a = s_hid[(r0 + r) * 65 + k];
            acc2[r][0] = fmaf(a, b.x, acc2[r][0]);
            acc2[r][1] = fmaf(a, b.y, acc2[r][1]);
            acc2[r][2] = fmaf(a, b.z, acc2[r][2]);
            acc2[r][3] = fmaf(a, b.w, acc2[r][3]);
        }
    }
#pragma unroll
    for (int r = 0; r < 8; r++) {
        int n = n0 + r0 + r;
        if (n >= N) break;
        float4 v;
        v.x = fmaxf(acc2[r][0] + s_b2[c0 + 0], 0.f);
        v.y = fmaxf(acc2[r][1] + s_b2[c0 + 1], 0.f);
        v.z = fmaxf(acc2[r][2] + s_b2[c0 + 2], 0.f);
        v.w = fmaxf(acc2[r][3] + s_b2[c0 + 3], 0.f);
        *(float4*)(g_h + (size_t)n * 64 + c0) = v;
    }
}

// ---------------------------------------------------------------------------
// k_pre (bf16 mma): [a_s|a_d] = h @ W', 128 nodes/block, warp = 16 rows x 128 cols.
// Outputs bf16x2 to g_as/g_ad. Zeroes g_agg.
// ---------------------------------------------------------------------------
__global__ __launch_bounds__(256) void k_pre(int layer, int N)
{
    __shared__ uint s_u[128 * 36];   // bf16x2 rows: 32 pairs + pad 4
    int tid = threadIdx.x;
    int n0 = blockIdx.x * 128;
    const uint* pw = p_w + layer * 12288;   // W' pairs [32][128]

    // stage h -> bf16x2 (4 uint4 tasks per thread) + zero g_agg
#pragma unroll
    for (int i = 0; i < 4; i++) {
        int lin = i * 256 + tid;
        int r = lin >> 3, q = lin & 7;         // row, uint4-quarter (8 bf16)
        int n = n0 + r;
        uint4 v = make_uint4(0u, 0u, 0u, 0u);
        if (n < N) {
            float4 a = __ldg((const float4*)(g_h + (size_t)n * 64 + q * 8));
            float4 b = __ldg((const float4*)(g_h + (size_t)n * 64 + q * 8 + 4));
            v.x = bpack(a.x, a.y); v.y = bpack(a.z, a.w);
            v.z = bpack(b.x, b.y); v.w = bpack(b.z, b.w);
        }
        *(uint4*)(s_u + r * 36 + q * 4) = v;
    }
#pragma unroll
    for (int i = 0; i < 8; i++) {
        int lin = i * 256 + tid;
        int r = lin >> 4, q = lin & 15;
        int n = n0 + r;
        if (n < N)
            *(float4*)(g_agg + (size_t)n * 64 + q * 4) = make_float4(0.f, 0.f, 0.f, 0.f);
    }
    __syncthreads();

    int warp = tid >> 5, lane = tid & 31;
    int m0 = warp * 16;
    int qrow = lane >> 2, qcol = lane & 3;

    float acc[16][4];
#pragma unroll
    for (int nt = 0; nt < 16; nt++)
#pragma unroll
        for (int c = 0; c < 4; c++) acc[nt][c] = 0.f;

    const uint* Au = s_u + (m0 + qrow) * 36 + qcol;
#pragma unroll
    for (int kt = 0; kt < 4; kt++) {
        uint a0 = Au[kt * 8];
        uint a1 = Au[kt * 8 + 8 * 36];
        uint a2 = Au[kt * 8 + 4];
        uint a3 = Au[kt * 8 + 4 + 8 * 36];
        const uint* B0 = pw + (kt * 8 + qcol) * 128 + qrow;
        const uint* B1 = B0 + 4 * 128;
#pragma unroll
        for (int nt = 0; nt < 16; nt++) {
            uint b0 = __ldg(B0 + nt * 8);
            uint b1 = __ldg(B1 + nt * 8);
            mma_bf16(acc[nt][0], acc[nt][1], acc[nt][2], acc[nt][3],
                     a0, a1, a2, a3, b0, b1);
        }
    }

    // write bf16x2: pair col = (nt*8 + 2*qcol)/2 = nt*4 + qcol
#pragma unroll
    for (int nt = 0; nt < 16; nt++) {
        int col = nt * 8 + qcol * 2;
        uint* base = (col < 64) ? g_as : g_ad;
        int cp = ((col < 64) ? col : col - 64) >> 1;
        int nA = n0 + m0 + qrow;
        int nB = nA + 8;
        if (nA < N) base[(size_t)nA * 32 + cp] = bpack(acc[nt][0], acc[nt][1]);
        if (nB < N) base[(size_t)nB * 32 + cp] = bpack(acc[nt][2], acc[nt][3]);
    }
}

// ---------------------------------------------------------------------------
// k_edge (bf16 mma): 256 threads, 128 edges/block.
//   bf16x2 gather+relu -> smem, mma m16n8k16, fp32 epilogue -> smem,
//   float4 atomic scatter.
// ---------------------------------------------------------------------------
__global__ __launch_bounds__(256) void k_edge(
    const int* __restrict__ src, const int* __restrict__ dst,
    const float* __restrict__ b1, int layer,
    const float* __restrict__ b2, int E)
{
    __shared__ float s_f[128 * 68];      // fp32 scatter stage; bf16 stage aliased below
    __shared__ uint s_b1p[32];
    __shared__ float s_b2[64];
    __shared__ int s_src[128], s_dst[128];
    uint* s_u = (uint*)s_f;              // bf16x2 stage: 128 rows * 36 uints (18KB < 34KB)
    int tid = threadIdx.x;
    int e0 = blockIdx.x * 128;
    const uint* pw = p_w + layer * 12288 + 4096;   // msg w2 pairs [32][64]

    if (tid < 32) s_b1p[tid] = bpack(b1[2 * tid], b1[2 * tid + 1]);
    else if (tid >= 64 && tid < 128) s_b2[tid - 64] = b2[tid - 64];
    if (tid >= 128) {
        int t = tid - 128;
        int e = e0 + t;
        bool v = (e < E);
        s_src[t] = v ? src[e] : -1;
        s_dst[t] = v ? dst[e] : -1;
    }
    __syncthreads();

    // gather + layer-1: 128 edges x 8 uint4 (8 bf16 each) = 1024 tasks
#pragma unroll
    for (int i = 0; i < 4; i++) {
        int lin = i * 256 + tid;
        int e = lin >> 3, q = lin & 7;
        int s = s_src[e];
        uint4 v = make_uint4(0u, 0u, 0u, 0u);
        if (s >= 0) {
            int d = s_dst[e];
            uint4 a = __ldg((const uint4*)(g_as + (size_t)s * 32 + q * 4));
            uint4 b = __ldg((const uint4*)(g_ad + (size_t)d * 32 + q * 4));
            v.x = brelu2(badd2(badd2(a.x, b.x), s_b1p[q * 4 + 0]));
            v.y = brelu2(badd2(badd2(a.y, b.y), s_b1p[q * 4 + 1]));
            v.z = brelu2(badd2(badd2(a.z, b.z), s_b1p[q * 4 + 2]));
            v.w = brelu2(badd2(badd2(a.w, b.w), s_b1p[q * 4 + 3]));
        }
        *(uint4*)(s_u + e * 36 + q * 4) = v;
    }
    __syncthreads();

    int warp = tid >> 5, lane = tid & 31;
    int m0 = warp * 16;
    int qrow = lane >> 2, qcol = lane & 3;

    float acc[8][4];
#pragma unroll
    for (int nt = 0; nt < 8; nt++)
#pragma unroll
        for (int c = 0; c < 4; c++) acc[nt][c] = 0.f;

    const uint* Au = s_u + (m0 + qrow) * 36 + qcol;
#pragma unroll
    for (int kt = 0; kt < 4; kt++) {
        uint a0 = Au[kt * 8];
        uint a1 = Au[kt * 8 + 8 * 36];
        uint a2 = Au[kt * 8 + 4];
        uint a3 = Au[kt * 8 + 4 + 8 * 36];
        const uint* B0 = pw + (kt * 8 + qcol) * 64 + qrow;
        const uint* B1 = B0 + 4 * 64;
#pragma unroll
        for (int nt = 0; nt < 8; nt++) {
            uint b0 = __ldg(B0 + nt * 8);
            uint b1v = __ldg(B1 + nt * 8);
            mma_bf16(acc[nt][0], acc[nt][1], acc[nt][2], acc[nt][3],
                     a0, a1, a2, a3, b0, b1v);
        }
    }
    __syncthreads();   // bf16 stage reads done; safe to overwrite as fp32

    // epilogue: bias + relu -> s_f (stride 68)
#pragma unroll
    for (int nt = 0; nt < 8; nt++) {
        int c = nt * 8 + qcol * 2;
        float bx = s_b2[c], by = s_b2[c + 1];
        float2 lo, hi;
        lo.x = fmaxf(acc[nt][0] + bx, 0.f);
        lo.y = fmaxf(acc[nt][1] + by, 0.f);
        hi.x = fmaxf(acc[nt][2] + bx, 0.f);
        hi.y = fmaxf(acc[nt][3] + by, 0.f);
        *(float2*)(s_f + (m0 + qrow) * 68 + c)     = lo;
        *(float2*)(s_f + (m0 + qrow + 8) * 68 + c) = hi;
    }
    __syncthreads();

    // scatter: 128 edges x 16 float4
#pragma unroll
    for (int i = 0; i < 8; i++) {
        int lin = i * 256 + tid;
        int e = lin >> 4, q = lin & 15;
        int d = s_dst[e];
        if (d >= 0) {
            float4 v = *(const float4*)(s_f + e * 68 + q * 4);
            atomicAdd((float4*)(g_agg + (size_t)d * 64 + q * 4), v);
        }
    }
}

// ---------------------------------------------------------------------------
// k_upd (bf16 mma): h = mlp2(concat(h, agg*inv)) in place. 128 nodes/block.
// ---------------------------------------------------------------------------
__global__ __launch_bounds__(256) void k_upd(
    int layer, const float* __restrict__ b1,
    const float* __restrict__ b2, int N)
{
    __shared__ uint s_u[128 * 68];   // phase1: 64 pairs + pad; phase2 aliased stride 36
    __shared__ float s_b1[64], s_b2[64];
    int tid = threadIdx.x;
    int n0 = blockIdx.x * 128;
    const uint* pw1 = p_w + layer * 12288 + 6144;    // upd w1 pairs [64][64]
    const uint* pw2 = p_w + layer * 12288 + 10240;   // upd w2 pairs [32][64]

    if (tid < 64) { s_b1[tid] = b1[tid]; s_b2[tid] = b2[tid]; }

    // stage concat(h, agg*inv) -> bf16x2: 128 rows x 16 uint4 tasks
#pragma unroll
    for (int i = 0; i < 8; i++) {
        int lin = i * 256 + tid;
        int r = lin >> 4, q = lin & 15;
        int n = n0 + r;
        uint4 v = make_uint4(0u, 0u, 0u, 0u);
        if (n < N) {
            if (q < 8) {
                float4 a = __ldg((const float4*)(g_h + (size_t)n * 64 + q * 8));
                float4 b = __ldg((const float4*)(g_h + (size_t)n * 64 + q * 8 + 4));
                v.x = bpack(a.x, a.y); v.y = bpack(a.z, a.w);
                v.z = bpack(b.x, b.y); v.w = bpack(b.z, b.w);
            } else {
                float iv = __ldg(g_inv + n);
                int qq = q - 8;
                float4 a = __ldg((const float4*)(g_agg + (size_t)n * 64 + qq * 8));
                float4 b = __ldg((const float4*)(g_agg + (size_t)n * 64 + qq * 8 + 4));
                v.x = bpack(a.x * iv, a.y * iv); v.y = bpack(a.z * iv, a.w * iv);
                v.z = bpack(b.x * iv, b.y * iv); v.w = bpack(b.z * iv, b.w * iv);
            }
        }
        *(uint4*)(s_u + r * 68 + q * 4) = v;
    }
    __syncthreads();

    int warp = tid >> 5, lane = tid & 31;
    int m0 = warp * 16;
    int qrow = lane >> 2, qcol = lane & 3;

    // phase 1: K=128 (8 k-tiles)
    float acc[8][4];
#pragma unroll
    for (int nt = 0; nt < 8; nt++)
#pragma unroll
        for (int c = 0; c < 4; c++) acc[nt][c] = 0.f;
    {
        const uint* Au = s_u + (m0 + qrow) * 68 + qcol;
#pragma unroll
        for (int kt = 0; kt < 8; kt++) {
            uint a0 = Au[kt * 8];
            uint a1 = Au[kt * 8 + 8 * 68];
            uint a2 = Au[kt * 8 + 4];
            uint a3 = Au[kt * 8 + 4 + 8 * 68];
            const uint* B0 = pw1 + (kt * 8 + qcol) * 64 + qrow;
            const uint* B1 = B0 + 4 * 64;
#pragma unroll
            for (int nt = 0; nt < 8; nt++) {
                uint b0 = __ldg(B0 + nt * 8);
                uint b1v = __ldg(B1 + nt * 8);
                mma_bf16(acc[nt][0], acc[nt][1], acc[nt][2], acc[nt][3],
                         a0, a1, a2, a3, b0, b1v);
            }
        }
    }
    __syncthreads();

    // hidden = relu(acc + b1) -> bf16x2, stride 36
#pragma unroll
    for (int nt = 0; nt < 8; nt++) {
        int c = nt * 8 + qcol * 2;
        float bx = s_b1[c], by = s_b1[c + 1];
        int cp = nt * 4 + qcol;
        s_u[(m0 + qrow) * 36 + cp] =
            bpack(fmaxf(acc[nt][0] + bx, 0.f), fmaxf(acc[nt][1] + by, 0.f));
        s_u[(m0 + qrow + 8) * 36 + cp] =
            bpack(fmaxf(acc[nt][2] + bx, 0.f), fmaxf(acc[nt][3] + by, 0.f));
    }
    __syncthreads();

    // phase 2: K=64 (4 k-tiles)
    float acc2[8][4];
#pragma unroll
    for (int nt = 0; nt < 8; nt++)
#pragma unroll
        for (int c = 0; c < 4; c++) acc2[nt][c] = 0.f;
    {
        const uint* Au = s_u + (m0 + qrow) * 36 + qcol;
#pragma unroll
        for (int kt = 0; kt < 4; kt++) {
            uint a0 = Au[kt * 8];
            uint a1 = Au[kt * 8 + 8 * 36];
            uint a2 = Au[kt * 8 + 4];
            uint a3 = Au[kt * 8 + 4 + 8 * 36];
            const uint* B0 = pw2 + (kt * 8 + qcol) * 64 + qrow;
            const uint* B1 = B0 + 4 * 64;
#pragma unroll
            for (int nt = 0; nt < 8; nt++) {
                uint b0 = __ldg(B0 + nt * 8);
                uint b1v = __ldg(B1 + nt * 8);
                mma_bf16(acc2[nt][0], acc2[nt][1], acc2[nt][2], acc2[nt][3],
                         a0, a1, a2, a3, b0, b1v);
            }
        }
    }

    // h = relu(acc2 + b2) -> g_h (fp32)
#pragma unroll
    for (int nt = 0; nt < 8; nt++) {
        int c = nt * 8 + qcol * 2;
        float bx = s_b2[c], by = s_b2[c + 1];
        int nA = n0 + m0 + qrow;
        int nB = nA + 8;
        if (nA < N) {
            float2 v;
            v.x = fmaxf(acc2[nt][0] + bx, 0.f);
            v.y = fmaxf(acc2[nt][1] + by, 0.f);
            *(float2*)(g_h + (size_t)nA * 64 + c) = v;
        }
        if (nB < N) {
            float2 v;
            v.x = fmaxf(acc2[nt][2] + bx, 0.f);
            v.y = fmaxf(acc2[nt][3] + by, 0.f);
            *(float2*)(g_h + (size_t)nB * 64 + c) = v;
        }
    }
}

// ---------------------------------------------------------------------------
// k_out: pred = relu(h@ow1+ob1)@ow2+ob2; out = 2*pi*sigmoid(pred), [N,3]
// ---------------------------------------------------------------------------
__global__ __launch_bounds__(128) void k_out(
    const float* __restrict__ w1, const float* __restrict__ b1,
    const float* __restrict__ w2, const float* __restrict__ b2,
    float* __restrict__ out, int N)
{
    extern __shared__ float sm[];
    float* s_h  = sm;             // 128 * 65
    float* s_w1 = sm + 128 * 65;  // 64 * 64
    __shared__ float s_b1[64], s_w2[64 * 3], s_b2[3];
    int tid = threadIdx.x;
    int n0 = blockIdx.x * 128;

    for (int i = tid; i < 4096; i += 128) s_w1[i] = w1[i];
    if (tid < 64) s_b1[tid] = b1[tid];
    for (int i = tid; i < 192; i += 128) s_w2[i] = w2[i];
    if (tid < 3) s_b2[tid] = b2[tid];
    for (int i = tid; i < 128 * 64; i += 128) {
        int r = i >> 6, k = i & 63;
        int n = n0 + r;
        s_h[r * 65 + k] = (n < N) ? g_h[(size_t)n * 64 + k] : 0.f;
    }
    __syncthreads();

    int n = n0 + tid;
    if (n >= N) return;

    float hrow[64];
#pragma unroll
    for (int k = 0; k < 64; k++) hrow[k] = s_h[tid * 65 + k];

    float hid[64];
#pragma unroll 4
    for (int j = 0; j < 64; j++) {
        float acc = s_b1[j];
#pragma unroll
        for (int k = 0; k < 64; k++) acc = fmaf(hrow[k], s_w1[k * 64 + j], acc);
        hid[j] = fmaxf(acc, 0.f);
    }
#pragma unroll
    for (int c = 0; c < 3; c++) {
        float acc = s_b2[c];
#pragma unroll
        for (int k = 0; k < 64; k++) acc = fmaf(hid[k], s_w2[k * 3 + c], acc);
        out[(size_t)n * 3 + c] = 6.283185307179586f / (1.f + expf(-acc));
    }
}

// ---------------------------------------------------------------------------
extern "C" void kernel_launch(void* const* d_in, const int* in_sizes, int n_in,
                              void* d_out, int out_size)
{
    const float* x      = (const float*)d_in[0];
    const int*   ei     = (const int*)  d_in[1];
    const float* enc_w1 = (const float*)d_in[2];
    const float* enc_b1 = (const float*)d_in[3];
    const float* enc_w2 = (const float*)d_in[4];
    const float* enc_b2 = (const float*)d_in[5];
    const float* msg_w1 = (const float*)d_in[6];
    const float* msg_b1 = (const float*)d_in[7];
    const float* msg_w2 = (const float*)d_in[8];
    const float* msg_b2 = (const float*)d_in[9];
    const float* upd_w1 = (const float*)d_in[10];
    const float* upd_b1 = (const float*)d_in[11];
    const float* upd_w2 = (const float*)d_in[12];
    const float* upd_b2 = (const float*)d_in[13];
    const float* out_w1 = (const float*)d_in[14];
    const float* out_b1 = (const float*)d_in[15];
    const float* out_w2 = (const float*)d_in[16];
    const float* out_b2 = (const float*)d_in[17];

    int N = in_sizes[0] / 5;
    int E = in_sizes[1] / 2;
    if (N > NMAX) N = NMAX;
    if (E > EMAX) E = EMAX;
    const int* src = ei;
    const int* dstp = ei + E;

    const int ENC_SM = (128 * 65 + 64 * 64) * 4;    // 49664
    const int OUT_SM = (128 * 65 + 64 * 64) * 4;    // 49664
    cudaFuncSetAttribute(k_encoder, cudaFuncAttributeMaxDynamicSharedMemorySize, ENC_SM);
    cudaFuncSetAttribute(k_out,  cudaFuncAttributeMaxDynamicSharedMemorySize, OUT_SM);

    int nbN256 = (N + 255) / 256;
    int nbE256 = (E + 255) / 256;
    int nbN128 = (N + 127) / 128;
    int nbE128 = (E + 127) / 128;

    k_pack<<<(3 * 12288 + 255) / 256, 256>>>(msg_w1, msg_w2, upd_w1, upd_w2);
    k_zero_cnt<<<nbN256, 256>>>(N);
    k_count<<<nbE256, 256>>>(dstp, E);
    k_inv<<<nbN256, 256>>>(N);
    k_encoder<<<nbN128, 256, ENC_SM>>>(x, enc_w1, enc_b1, enc_w2, enc_b2, N);

    for (int l = 0; l < 3; l++) {
        k_pre<<<nbN128, 256>>>(l, N);
        k_edge<<<nbE128, 256>>>(src, dstp, msg_b1 + l * 64, l,
                                msg_b2 + l * 64, E);
        k_upd<<<nbN128, 256>>>(l, upd_b1 + l * 64, upd_b2 + l * 64, N);
    }

    k_out<<<nbN128, 128, OUT_SM>>>(out_w1, out_b1, out_w2, out_b2,
                                   (float*)d_out, N);
}

// round 9
// speedup vs baseline: 2.9652x; 1.0921x over previous
#include <cuda_runtime.h>
#include <cuda_bf16.h>

// ---------------------------------------------------------------------------
// FixedSimpleGNN: 3-layer MPNN, N=100000, E=1000000, H=64.
//   Factorized message layer-1 (per-node a_s/a_d bf16x2, fused into the
//   producing kernel's epilogue), per-edge bf16 mma.m16n8k16 layer-2,
//   v4.bf16x2 vector-red scatter, bf16 mma update MLP.
// ---------------------------------------------------------------------------

#define NMAX 100000
#define EMAX 1000000

typedef unsigned int uint;

__device__ float g_h  [NMAX * 64];
__device__ uint  g_as [NMAX * 32];   // bf16x2 pairs
__device__ uint  g_ad [NMAX * 32];   // bf16x2 pairs
__device__ uint  g_agg[NMAX * 32];   // bf16x2 pairs (atomic accum)
__device__ float g_cnt[NMAX];
__device__ float g_inv[NMAX];

// packed bf16x2 weights, per layer (12288 uints each):
//   [0,4096):      msg W' pairs  [32][128]
//   [4096,6144):   msg w2 pairs  [32][64]
//   [6144,10240):  upd w1 pairs  [64][64]
//   [10240,12288): upd w2 pairs  [32][64]
__device__ uint p_w[3 * 12288];

__device__ __forceinline__ uint bpack(float lo, float hi) {
    __nv_bfloat162 p = __floats2bfloat162_rn(lo, hi);
    return *(uint*)&p;
}
__device__ __forceinline__ float2 bunpack(uint v) {
    return __bfloat1622float2(*(__nv_bfloat162*)&v);
}
__device__ __forceinline__ uint badd2(uint a, uint b) {
    __nv_bfloat162 r = __hadd2(*(__nv_bfloat162*)&a, *(__nv_bfloat162*)&b);
    return *(uint*)&r;
}
__device__ __forceinline__ uint brelu2(uint a) {
    __nv_bfloat162 z = __float2bfloat162_rn(0.f);
    __nv_bfloat162 r = __hmax2(*(__nv_bfloat162*)&a, z);
    return *(uint*)&r;
}
__device__ __forceinline__ void mma_bf16(
    float& c0, float& c1, float& c2, float& c3,
    uint a0, uint a1, uint a2, uint a3, uint b0, uint b1)
{
    asm volatile(
        "mma.sync.aligned.m16n8k16.row.col.f32.bf16.bf16.f32 "
        "{%0,%1,%2,%3}, {%4,%5,%6,%7}, {%8,%9}, {%0,%1,%2,%3};"
        : "+f"(c0), "+f"(c1), "+f"(c2), "+f"(c3)
        : "r"(a0), "r"(a1), "r"(a2), "r"(a3), "r"(b0), "r"(b1));
}
__device__ __forceinline__ void red_v4_bf16(uint* addr, uint4 v) {
    asm volatile(
        "red.global.add.noftz.v4.bf16x2 [%0], {%1,%2,%3,%4};"
        :: "l"(addr), "r"(v.x), "r"(v.y), "r"(v.z), "r"(v.w) : "memory");
}

// ---------------------------------------------------------------------------
// k_pack: build bf16x2 B-fragment weight arrays
// ---------------------------------------------------------------------------
__global__ void k_pack(const float* __restrict__ msg_w1,
                       const float* __restrict__ msg_w2,
                       const float* __restrict__ upd_w1,
                       const float* __restrict__ upd_w2)
{
    int idx = blockIdx.x * blockDim.x + threadIdx.x;
    if (idx >= 3 * 12288) return;
    int l = idx / 12288, r = idx % 12288;
    const float* mw1 = msg_w1 + l * 8192;
    const float* mw2 = msg_w2 + l * 4096;
    const float* uw1 = upd_w1 + l * 8192;
    const float* uw2 = upd_w2 + l * 4096;
    float lo, hi;
    if (r < 4096) {
        int kk = r >> 7, j = r & 127;
        if (j < 64) { lo = mw1[(2*kk)*64 + j];          hi = mw1[(2*kk+1)*64 + j]; }
        else        { lo = mw1[(64+2*kk)*64 + (j-64)];  hi = mw1[(64+2*kk+1)*64 + (j-64)]; }
    } else if (r < 6144) {
        int t = r - 4096; int kk = t >> 6, n = t & 63;
        lo = mw2[2*kk*64 + n]; hi = mw2[(2*kk+1)*64 + n];
    } else if (r < 10240) {
        int t = r - 6144; int kk = t >> 6, n = t & 63;
        lo = uw1[2*kk*64 + n]; hi = uw1[(2*kk+1)*64 + n];
    } else {
        int t = r - 10240; int kk = t >> 6, n = t & 63;
        lo = uw2[2*kk*64 + n]; hi = uw2[(2*kk+1)*64 + n];
    }
    p_w[idx] = bpack(lo, hi);
}

// ---------------------------------------------------------------------------
__global__ void k_zero_cnt(int N) {
    int i = blockIdx.x * blockDim.x + threadIdx.x;
    if (i < N) g_cnt[i] = 0.f;
}
__global__ void k_count(const int* __restrict__ dst, int E) {
    int e = blockIdx.x * blockDim.x + threadIdx.x;
    if (e < E) atomicAdd(&g_cnt[dst[e]], 1.f);
}
__global__ void k_inv(int N) {
    int i = blockIdx.x * blockDim.x + threadIdx.x;
    if (i < N) g_inv[i] = 1.f / fmaxf(g_cnt[i], 1.f);
}

// ---------------------------------------------------------------------------
// pre-phase mma (shared by encoder & k_upd epilogues):
// A = bf16 h rows in s_u (stride 36), B = W' pairs [32][128] of given layer.
// Warp covers rows m0..m0+15, all 128 cols. Writes g_as/g_ad bf16 pairs.
// ---------------------------------------------------------------------------
__device__ __forceinline__ void pre_mma(
    const uint* s_u, const uint* pw, int n0, int m0, int qrow, int qcol, int N)
{
    float acc[16][4];
#pragma unroll
    for (int nt = 0; nt < 16; nt++)
#pragma unroll
        for (int c = 0; c < 4; c++) acc[nt][c] = 0.f;

    const uint* Au = s_u + (m0 + qrow) * 36 + qcol;
#pragma unroll
    for (int kt = 0; kt < 4; kt++) {
        uint a0 = Au[kt * 8];
        uint a1 = Au[kt * 8 + 8 * 36];
        uint a2 = Au[kt * 8 + 4];
        uint a3 = Au[kt * 8 + 4 + 8 * 36];
        const uint* B0 = pw + (kt * 8 + qcol) * 128 + qrow;
        const uint* B1 = B0 + 4 * 128;
#pragma unroll
        for (int nt = 0; nt < 16; nt++) {
            uint b0 = __ldg(B0 + nt * 8);
            uint b1 = __ldg(B1 + nt * 8);
            mma_bf16(acc[nt][0], acc[nt][1], acc[nt][2], acc[nt][3],
                     a0, a1, a2, a3, b0, b1);
        }
    }
#pragma unroll
    for (int nt = 0; nt < 16; nt++) {
        int col = nt * 8 + qcol * 2;
        uint* base = (col < 64) ? g_as : g_ad;
        int cp = ((col < 64) ? col : col - 64) >> 1;
        int nA = n0 + m0 + qrow;
        int nB = nA + 8;
        if (nA < N) base[(size_t)nA * 32 + cp] = bpack(acc[nt][0], acc[nt][1]);
        if (nB < N) base[(size_t)nB * 32 + cp] = bpack(acc[nt][2], acc[nt][3]);
    }
}

// ---------------------------------------------------------------------------
// encoder (+ fused pre for layer 0): h = mlp2(x), a_s/a_d = h @ W'_0.
// Zeroes g_agg. 256 threads, 128 nodes/block.
// ---------------------------------------------------------------------------
__global__ __launch_bounds__(256) void k_encoder(
    const float* __restrict__ x,
    const float* __restrict__ w1, const float* __restrict__ b1,
    const float* __restrict__ w2, const float* __restrict__ b2, int N)
{
    extern __shared__ float sm[];
    float* s_hid = sm;             // 128 * 65
    float* s_w2  = sm + 128 * 65;  // 64 * 64
    uint*  s_u   = (uint*)sm;      // pre-phase bf16 stage (alias, 128*36)
    __shared__ float s_w1[5 * 64], s_b1[64], s_b2[64];
    __shared__ float s_x[128 * 6];
    int tid = threadIdx.x;
    int n0 = blockIdx.x * 128;

    for (int i = tid; i < 5 * 64; i += 256)  s_w1[i] = w1[i];
    for (int i = tid; i < 64 * 64; i += 256) s_w2[i] = w2[i];
    if (tid < 64) { s_b1[tid] = b1[tid]; s_b2[tid] = b2[tid]; }
    for (int i = tid; i < 128 * 5; i += 256) {
        int r = i / 5, k = i % 5;
        int n = n0 + r;
        s_x[r * 6 + k] = (n < N) ? x[(size_t)n * 5 + k] : 0.f;
    }
    // zero g_agg (bf16 pairs): 128 rows x 8 uint4
#pragma unroll
    for (int i = 0; i < 4; i++) {
        int lin = i * 256 + tid;
        int r = lin >> 3, q = lin & 7;
        int n = n0 + r;
        if (n < N)
            *(uint4*)(g_agg + (size_t)n * 32 + q * 4) = make_uint4(0u, 0u, 0u, 0u);
    }
    __syncthreads();

    int r0 = (tid >> 4) * 8;
    int c0 = (tid & 15) * 4;

    float acc[8][4];
#pragma unroll
    for (int r = 0; r < 8; r++)
#pragma unroll
        for (int c = 0; c < 4; c++) acc[r][c] = 0.f;
#pragma unroll
    for (int k = 0; k < 5; k++) {
        float4 b = *(const float4*)(s_w1 + k * 64 + c0);
#pragma unroll
        for (int r = 0; r < 8; r++) {
            float a = s_x[(r0 + r) * 6 + k];
            acc[r][0] = fmaf(a, b.x, acc[r][0]);
            acc[r][1] = fmaf(a, b.y, acc[r][1]);
            acc[r][2] = fmaf(a, b.z, acc[r][2]);
            acc[r][3] = fmaf(a, b.w, acc[r][3]);
        }
    }
#pragma unroll
    for (int r = 0; r < 8; r++)
#pragma unroll
        for (int c = 0; c < 4; c++)
            s_hid[(r0 + r) * 65 + c0 + c] = fmaxf(acc[r][c] + s_b1[c0 + c], 0.f);
    __syncthreads();

    float acc2[8][4];
#pragma unroll
    for (int r = 0; r < 8; r++)
#pragma unroll
        for (int c = 0; c < 4; c++) acc2[r][c] = 0.f;
#pragma unroll 4
    for (int k = 0; k < 64; k++) {
        float4 b = *(const float4*)(s_w2 + k * 64 + c0);
#pragma unroll
        for (int r = 0; r < 8; r++) {
            float a = s_hid[(r0 + r) * 65 + k];
            acc2[r][0] = fmaf(a, b.x, acc2[r][0]);
            acc2[r][1] = fmaf(a, b.y, acc2[r][1]);
            acc2[r][2] = fmaf(a, b.z, acc2[r][2]);
            acc2[r][3] = fmaf(a, b.w, acc2[r][3]);
        }
    }
    __syncthreads();   // all reads of s_hid/s_w2 done; s_u overwrite safe

    // epilogue: h -> g_h (fp32) + s_u (bf16 pairs)
#pragma unroll
    for (int r = 0; r < 8; r++) {
        int n = n0 + r0 + r;
        float4 v;
        v.x = fmaxf(acc2[r][0] + s_b2[c0 + 0], 0.f);
        v.y = fmaxf(acc2[r][1] + s_b2[c0 + 1], 0.f);
        v.z = fmaxf(acc2[r][2] + s_b2[c0 + 2], 0.f);
        v.w = fmaxf(acc2[r][3] + s_b2[c0 + 3], 0.f);
        if (n < N) *(float4*)(g_h + (size_t)n * 64 + c0) = v;
        s_u[(r0 + r) * 36 + (c0 >> 1)]     = bpack(v.x, v.y);
        s_u[(r0 + r) * 36 + (c0 >> 1) + 1] = bpack(v.z, v.w);
    }
    __syncthreads();

    // fused pre-phase for layer 0
    int warp = tid >> 5, lane = tid & 31;
    pre_mma(s_u, p_w, n0, warp * 16, lane >> 2, lane & 3, N);
}

// ---------------------------------------------------------------------------
// k_edge: 256 threads, 128 edges/block.
//   bf16x2 gather+relu -> smem, mma m16n8k16, bf16 epilogue -> smem,
//   v4.bf16x2 red scatter into g_agg.
// ---------------------------------------------------------------------------
__global__ __launch_bounds__(256) void k_edge(
    const int* __restrict__ src, const int* __restrict__ dst,
    const float* __restrict__ b1, int layer,
    const float* __restrict__ b2, int E)
{
    __shared__ uint s_u[128 * 36];
    __shared__ uint s_b1p[32];
    __shared__ float s_b2[64];
    __shared__ int s_src[128], s_dst[128];
    int tid = threadIdx.x;
    int e0 = blockIdx.x * 128;
    const uint* pw = p_w + layer * 12288 + 4096;   // msg w2 pairs [32][64]

    if (tid < 32) s_b1p[tid] = bpack(b1[2 * tid], b1[2 * tid + 1]);
    else if (tid >= 64 && tid < 128) s_b2[tid - 64] = b2[tid - 64];
    if (tid >= 128) {
        int t = tid - 128;
        int e = e0 + t;
        bool v = (e < E);
        s_src[t] = v ? src[e] : -1;
        s_dst[t] = v ? dst[e] : -1;
    }
    __syncthreads();

    // gather + layer-1: 128 edges x 8 uint4
#pragma unroll
    for (int i = 0; i < 4; i++) {
        int lin = i * 256 + tid;
        int e = lin >> 3, q = lin & 7;
        int s = s_src[e];
        uint4 v = make_uint4(0u, 0u, 0u, 0u);
        if (s >= 0) {
            int d = s_dst[e];
            uint4 a = __ldg((const uint4*)(g_as + (size_t)s * 32 + q * 4));
            uint4 b = __ldg((const uint4*)(g_ad + (size_t)d * 32 + q * 4));
            v.x = brelu2(badd2(badd2(a.x, b.x), s_b1p[q * 4 + 0]));
            v.y = brelu2(badd2(badd2(a.y, b.y), s_b1p[q * 4 + 1]));
            v.z = brelu2(badd2(badd2(a.z, b.z), s_b1p[q * 4 + 2]));
            v.w = brelu2(badd2(badd2(a.w, b.w), s_b1p[q * 4 + 3]));
        }
        *(uint4*)(s_u + e * 36 + q * 4) = v;
    }
    __syncthreads();

    int warp = tid >> 5, lane = tid & 31;
    int m0 = warp * 16;
    int qrow = lane >> 2, qcol = lane & 3;

    float acc[8][4];
#pragma unroll
    for (int nt = 0; nt < 8; nt++)
#pragma unroll
        for (int c = 0; c < 4; c++) acc[nt][c] = 0.f;

    const uint* Au = s_u + (m0 + qrow) * 36 + qcol;
#pragma unroll
    for (int kt = 0; kt < 4; kt++) {
        uint a0 = Au[kt * 8];
        uint a1 = Au[kt * 8 + 8 * 36];
        uint a2 = Au[kt * 8 + 4];
        uint a3 = Au[kt * 8 + 4 + 8 * 36];
        const uint* B0 = pw + (kt * 8 + qcol) * 64 + qrow;
        const uint* B1 = B0 + 4 * 64;
#pragma unroll
        for (int nt = 0; nt < 8; nt++) {
            uint b0 = __ldg(B0 + nt * 8);
            uint b1v = __ldg(B1 + nt * 8);
            mma_bf16(acc[nt][0], acc[nt][1], acc[nt][2], acc[nt][3],
                     a0, a1, a2, a3, b0, b1v);
        }
    }

    // epilogue: m = relu(acc + b2) -> s_u (bf16 pairs, own rows only)
#pragma unroll
    for (int nt = 0; nt < 8; nt++) {
        int c = nt * 8 + qcol * 2;
        float bx = s_b2[c], by = s_b2[c + 1];
        int cp = nt * 4 + qcol;
        s_u[(m0 + qrow) * 36 + cp] =
            bpack(fmaxf(acc[nt][0] + bx, 0.f), fmaxf(acc[nt][1] + by, 0.f));
        s_u[(m0 + qrow + 8) * 36 + cp] =
            bpack(fmaxf(acc[nt][2] + bx, 0.f), fmaxf(acc[nt][3] + by, 0.f));
    }
    __syncthreads();

    // scatter: 128 edges x 8 uint4 vector reds
#pragma unroll
    for (int i = 0; i < 4; i++) {
        int lin = i * 256 + tid;
        int e = lin >> 3, q = lin & 7;
        int d = s_dst[e];
        if (d >= 0) {
            uint4 v = *(const uint4*)(s_u + e * 36 + q * 4);
            red_v4_bf16(g_agg + (size_t)d * 32 + q * 4, v);
        }
    }
}

// ---------------------------------------------------------------------------
// k_upd (+ fused pre for layer l+1): h = mlp2(concat(h, agg*inv)); zeroes
// g_agg rows for next layer; if has_next, computes a_s/a_d with next W'.
// ---------------------------------------------------------------------------
__global__ __launch_bounds__(256) void k_upd(
    int layer, const float* __restrict__ b1,
    const float* __restrict__ b2, int has_next, int N)
{
    __shared__ uint s_u[128 * 68];   // phase1 stride 68; later stride 36
    __shared__ float s_b1[64], s_b2[64];
    int tid = threadIdx.x;
    int n0 = blockIdx.x * 128;
    const uint* pw1 = p_w + layer * 12288 + 6144;    // upd w1 pairs [64][64]
    const uint* pw2 = p_w + layer * 12288 + 10240;   // upd w2 pairs [32][64]

    if (tid < 64) { s_b1[tid] = b1[tid]; s_b2[tid] = b2[tid]; }

    // stage concat(h, agg*inv) -> bf16x2 (stride 68); zero g_agg rows
#pragma unroll
    for (int i = 0; i < 8; i++) {
        int lin = i * 256 + tid;
        int r = lin >> 4, q = lin & 15;
        int n = n0 + r;
        uint4 v = make_uint4(0u, 0u, 0u, 0u);
        if (n < N) {
            if (q < 8) {
                float4 a = __ldg((const float4*)(g_h + (size_t)n * 64 + q * 8));
                float4 b = __ldg((const float4*)(g_h + (size_t)n * 64 + q * 8 + 4));
                v.x = bpack(a.x, a.y); v.y = bpack(a.z, a.w);
                v.z = bpack(b.x, b.y); v.w = bpack(b.z, b.w);
            } else {
                float iv = __ldg(g_inv + n);
                int qq = q - 8;
                uint4 a = *(const uint4*)(g_agg + (size_t)n * 32 + qq * 4);
                float2 p0 = bunpack(a.x), p1 = bunpack(a.y);
                float2 p2 = bunpack(a.z), p3 = bunpack(a.w);
                v.x = bpack(p0.x * iv, p0.y * iv);
                v.y = bpack(p1.x * iv, p1.y * iv);
                v.z = bpack(p2.x * iv, p2.y * iv);
                v.w = bpack(p3.x * iv, p3.y * iv);
                *(uint4*)(g_agg + (size_t)n * 32 + qq * 4) = make_uint4(0u, 0u, 0u, 0u);
            }
        }
        *(uint4*)(s_u + r * 68 + q * 4) = v;
    }
    __syncthreads();

    int warp = tid >> 5, lane = tid & 31;
    int m0 = warp * 16;
    int qrow = lane >> 2, qcol = lane & 3;

    // phase 1: K=128
    float acc[8][4];
#pragma unroll
    for (int nt = 0; nt < 8; nt++)
#pragma unroll
        for (int c = 0; c < 4; c++) acc[nt][c] = 0.f;
    {
        const uint* Au = s_u + (m0 + qrow) * 68 + qcol;
#pragma unroll
        for (int kt = 0; kt < 8; kt++) {
            uint a0 = Au[kt * 8];
            uint a1 = Au[kt * 8 + 8 * 68];
            uint a2 = Au[kt * 8 + 4];
            uint a3 = Au[kt * 8 + 4 + 8 * 68];
            const uint* B0 = pw1 + (kt * 8 + qcol) * 64 + qrow;
            const uint* B1 = B0 + 4 * 64;
#pragma unroll
            for (int nt = 0; nt < 8; nt++) {
                uint b0 = __ldg(B0 + nt * 8);
                uint b1v = __ldg(B1 + nt * 8);
                mma_bf16(acc[nt][0], acc[nt][1], acc[nt][2], acc[nt][3],
                         a0, a1, a2, a3, b0, b1v);
            }
        }
    }
    __syncthreads();

    // hidden = relu(acc + b1) -> bf16x2, stride 36
#pragma unroll
    for (int nt = 0; nt < 8; nt++) {
        int c = nt * 8 + qcol * 2;
        float bx = s_b1[c], by = s_b1[c + 1];
        int cp = nt * 4 + qcol;
        s_u[(m0 + qrow) * 36 + cp] =
            bpack(fmaxf(acc[nt][0] + bx, 0.f), fmaxf(acc[nt][1] + by, 0.f));
        s_u[(m0 + qrow + 8) * 36 + cp] =
            bpack(fmaxf(acc[nt][2] + bx, 0.f), fmaxf(acc[nt][3] + by, 0.f));
    }
    __syncthreads();

    // phase 2: K=64
    float acc2[8][4];
#pragma unroll
    for (int nt = 0; nt < 8; nt++)
#pragma unroll
        for (int c = 0; c < 4; c++) acc2[nt][c] = 0.f;
    {
        const uint* Au = s_u + (m0 + qrow) * 36 + qcol;
#pragma unroll
        for (int kt = 0; kt < 4; kt++) {
            uint a0 = Au[kt * 8];
            uint a1 = Au[kt * 8 + 8 * 36];
            uint a2 = Au[kt * 8 + 4];
            uint a3 = Au[kt * 8 + 4 + 8 * 36];
            const uint* B0 = pw2 + (kt * 8 + qcol) * 64 + qrow;
            const uint* B1 = B0 + 4 * 64;
#pragma unroll
            for (int nt = 0; nt < 8; nt++) {
                uint b0 = __ldg(B0 + nt * 8);
                uint b1v = __ldg(B1 + nt * 8);
                mma_bf16(acc2[nt][0], acc2[nt][1], acc2[nt][2], acc2[nt][3],
                         a0, a1, a2, a3, b0, b1v);
            }
        }
    }

    // h = relu(acc2 + b2) -> g_h (fp32) + s_u (bf16, own rows, stride 36)
#pragma unroll
    for (int nt = 0; nt < 8; nt++) {
        int c = nt * 8 + qcol * 2;
        float bx = s_b2[c], by = s_b2[c + 1];
        int cp = nt * 4 + qcol;
        int nA = n0 + m0 + qrow;
        int nB = nA + 8;
        float2 vA, vB;
        vA.x = fmaxf(acc2[nt][0] + bx, 0.f);
        vA.y = fmaxf(acc2[nt][1] + by, 0.f);
        vB.x = fmaxf(acc2[nt][2] + bx, 0.f);
        vB.y = fmaxf(acc2[nt][3] + by, 0.f);
        if (nA < N) *(float2*)(g_h + (size_t)nA * 64 + c) = vA;
        if (nB < N) *(float2*)(g_h + (size_t)nB * 64 + c) = vB;
        s_u[(m0 + qrow) * 36 + cp]     = bpack(vA.x, vA.y);
        s_u[(m0 + qrow + 8) * 36 + cp] = bpack(vB.x, vB.y);
    }

    // fused pre-phase for next layer (reads own warp rows only; no sync needed)
    if (has_next)
        pre_mma(s_u, p_w + (layer + 1) * 12288, n0, m0, qrow, qcol, N);
}

// ---------------------------------------------------------------------------
// k_out: pred = relu(h@ow1+ob1)@ow2+ob2; out = 2*pi*sigmoid(pred), [N,3]
// ---------------------------------------------------------------------------
__global__ __launch_bounds__(128) void k_out(
    const float* __restrict__ w1, const float* __restrict__ b1,
    const float* __restrict__ w2, const float* __restrict__ b2,
    float* __restrict__ out, int N)
{
    extern __shared__ float sm[];
    float* s_h  = sm;             // 128 * 65
    float* s_w1 = sm + 128 * 65;  // 64 * 64
    __shared__ float s_b1[64], s_w2[64 * 3], s_b2[3];
    int tid = threadIdx.x;
    int n0 = blockIdx.x * 128;

    for (int i = tid; i < 4096; i += 128) s_w1[i] = w1[i];
    if (tid < 64) s_b1[tid] = b1[tid];
    for (int i = tid; i < 192; i += 128) s_w2[i] = w2[i];
    if (tid < 3) s_b2[tid] = b2[tid];
    for (int i = tid; i < 128 * 64; i += 128) {
        int r = i >> 6, k = i & 63;
        int n = n0 + r;
        s_h[r * 65 + k] = (n < N) ? g_h[(size_t)n * 64 + k] : 0.f;
    }
    __syncthreads();

    int n = n0 + tid;
    if (n >= N) return;

    float hrow[64];
#pragma unroll
    for (int k = 0; k < 64; k++) hrow[k] = s_h[tid * 65 + k];

    float hid[64];
#pragma unroll 4
    for (int j = 0; j < 64; j++) {
        float acc = s_b1[j];
#pragma unroll
        for (int k = 0; k < 64; k++) acc = fmaf(hrow[k], s_w1[k * 64 + j], acc);
        hid[j] = fmaxf(acc, 0.f);
    }
#pragma unroll
    for (int c = 0; c < 3; c++) {
        float acc = s_b2[c];
#pragma unroll
        for (int k = 0; k < 64; k++) acc = fmaf(hid[k], s_w2[k * 3 + c], acc);
        out[(size_t)n * 3 + c] = 6.283185307179586f / (1.f + expf(-acc));
    }
}

// ---------------------------------------------------------------------------
extern "C" void kernel_launch(void* const* d_in, const int* in_sizes, int n_in,
                              void* d_out, int out_size)
{
    const float* x      = (const float*)d_in[0];
    const int*   ei     = (const int*)  d_in[1];
    const float* enc_w1 = (const float*)d_in[2];
    const float* enc_b1 = (const float*)d_in[3];
    const float* enc_w2 = (const float*)d_in[4];
    const float* enc_b2 = (const float*)d_in[5];
    const float* msg_w1 = (const float*)d_in[6];
    const float* msg_b1 = (const float*)d_in[7];
    const float* msg_w2 = (const float*)d_in[8];
    const float* msg_b2 = (const float*)d_in[9];
    const float* upd_w1 = (const float*)d_in[10];
    const float* upd_b1 = (const float*)d_in[11];
    const float* upd_w2 = (const float*)d_in[12];
    const float* upd_b2 = (const float*)d_in[13];
    const float* out_w1 = (const float*)d_in[14];
    const float* out_b1 = (const float*)d_in[15];
    const float* out_w2 = (const float*)d_in[16];
    const float* out_b2 = (const float*)d_in[17];

    int N = in_sizes[0] / 5;
    int E = in_sizes[1] / 2;
    if (N > NMAX) N = NMAX;
    if (E > EMAX) E = EMAX;
    const int* src = ei;
    const int* dstp = ei + E;

    const int ENC_SM = (128 * 65 + 64 * 64) * 4;    // 49664
    const int OUT_SM = (128 * 65 + 64 * 64) * 4;    // 49664
    cudaFuncSetAttribute(k_encoder, cudaFuncAttributeMaxDynamicSharedMemorySize, ENC_SM);
    cudaFuncSetAttribute(k_out,  cudaFuncAttributeMaxDynamicSharedMemorySize, OUT_SM);

    int nbN256 = (N + 255) / 256;
    int nbE256 = (E + 255) / 256;
    int nbN128 = (N + 127) / 128;
    int nbE128 = (E + 127) / 128;

    k_pack<<<(3 * 12288 + 255) / 256, 256>>>(msg_w1, msg_w2, upd_w1, upd_w2);
    k_zero_cnt<<<nbN256, 256>>>(N);
    k_count<<<nbE256, 256>>>(dstp, E);
    k_inv<<<nbN256, 256>>>(N);
    k_encoder<<<nbN128, 256, ENC_SM>>>(x, enc_w1, enc_b1, enc_w2, enc_b2, N);

    for (int l = 0; l < 3; l++) {
        k_edge<<<nbE128, 256>>>(src, dstp, msg_b1 + l * 64, l,
                                msg_b2 + l * 64, E);
        k_upd<<<nbN128, 256>>>(l, upd_b1 + l * 64, upd_b2 + l * 64,
                               (l < 2) ? 1 : 0, N);
    }

    k_out<<<nbN128, 128, OUT_SM>>>(out_w1, out_b1, out_w2, out_b2,
                                   (float*)d_out, N);
}

// round 11
// speedup vs baseline: 3.2139x; 1.0838x over previous
#include <cuda_runtime.h>
#include <cuda_bf16.h>

// ---------------------------------------------------------------------------
// FixedSimpleGNN: 3-layer MPNN, N=100000, E=1000000, H=64.
//   - per-node a_s/a_d (factorized msg layer-1), bf16x2, fused into producer
//   - per-edge bf16 mma.m16n8k16 msg layer-2, warp-local (no block barriers)
//   - v4.bf16x2 red scatter
//   - warp-local bf16 mma update MLP; output head fused into last update
// ---------------------------------------------------------------------------

#define NMAX 100000
#define EMAX 1000000

typedef unsigned int uint;

__device__ uint  g_hb [NMAX * 32];   // h, bf16x2 pairs
__device__ uint  g_as [NMAX * 32];   // bf16x2 pairs
__device__ uint  g_ad [NMAX * 32];   // bf16x2 pairs
__device__ uint  g_agg[NMAX * 32];   // bf16x2 pairs (atomic accum)
__device__ float g_cnt[NMAX];
__device__ float g_inv[NMAX];

// packed bf16x2 weights, per layer (12288 uints each), + out_w1 at the end:
//   layer l*12288 + [0,4096):      msg W' pairs  [32][128]
//   layer l*12288 + [4096,6144):   msg w2 pairs  [32][64]
//   layer l*12288 + [6144,10240):  upd w1 pairs  [64][64]
//   layer l*12288 + [10240,12288): upd w2 pairs  [32][64]
//   [36864,38912): out w1 pairs [32][64]
__device__ uint p_w[3 * 12288 + 2048];

__device__ __forceinline__ uint bpack(float lo, float hi) {
    __nv_bfloat162 p = __floats2bfloat162_rn(lo, hi);
    return *(uint*)&p;
}
__device__ __forceinline__ float2 bunpack(uint v) {
    return __bfloat1622float2(*(__nv_bfloat162*)&v);
}
__device__ __forceinline__ uint badd2(uint a, uint b) {
    __nv_bfloat162 r = __hadd2(*(__nv_bfloat162*)&a, *(__nv_bfloat162*)&b);
    return *(uint*)&r;
}
__device__ __forceinline__ uint brelu2(uint a) {
    __nv_bfloat162 z = __float2bfloat162_rn(0.f);
    __nv_bfloat162 r = __hmax2(*(__nv_bfloat162*)&a, z);
    return *(uint*)&r;
}
__device__ __forceinline__ void mma_bf16(
    float& c0, float& c1, float& c2, float& c3,
    uint a0, uint a1, uint a2, uint a3, uint b0, uint b1)
{
    asm volatile(
        "mma.sync.aligned.m16n8k16.row.col.f32.bf16.bf16.f32 "
        "{%0,%1,%2,%3}, {%4,%5,%6,%7}, {%8,%9}, {%0,%1,%2,%3};"
        : "+f"(c0), "+f"(c1), "+f"(c2), "+f"(c3)
        : "r"(a0), "r"(a1), "r"(a2), "r"(a3), "r"(b0), "r"(b1));
}
__device__ __forceinline__ void red_v4_bf16(uint* addr, uint4 v) {
    asm volatile(
        "red.global.add.noftz.v4.bf16x2 [%0], {%1,%2,%3,%4};"
        :: "l"(addr), "r"(v.x), "r"(v.y), "r"(v.z), "r"(v.w) : "memory");
}

// ---------------------------------------------------------------------------
// k_pack: build bf16x2 B-fragment weight arrays (incl. out_w1)
// ---------------------------------------------------------------------------
__global__ void k_pack(const float* __restrict__ msg_w1,
                       const float* __restrict__ msg_w2,
                       const float* __restrict__ upd_w1,
                       const float* __restrict__ upd_w2,
                       const float* __restrict__ out_w1)
{
    int idx = blockIdx.x * blockDim.x + threadIdx.x;
    if (idx >= 3 * 12288 + 2048) return;
    float lo, hi;
    if (idx >= 3 * 12288) {
        int t = idx - 3 * 12288; int kk = t >> 6, n = t & 63;
        lo = out_w1[2*kk*64 + n]; hi = out_w1[(2*kk+1)*64 + n];
        p_w[idx] = bpack(lo, hi);
        return;
    }
    int l = idx / 12288, r = idx % 12288;
    const float* mw1 = msg_w1 + l * 8192;
    const float* mw2 = msg_w2 + l * 4096;
    const float* uw1 = upd_w1 + l * 8192;
    const float* uw2 = upd_w2 + l * 4096;
    if (r < 4096) {
        int kk = r >> 7, j = r & 127;
        if (j < 64) { lo = mw1[(2*kk)*64 + j];          hi = mw1[(2*kk+1)*64 + j]; }
        else        { lo = mw1[(64+2*kk)*64 + (j-64)];  hi = mw1[(64+2*kk+1)*64 + (j-64)]; }
    } else if (r < 6144) {
        int t = r - 4096; int kk = t >> 6, n = t & 63;
        lo = mw2[2*kk*64 + n]; hi = mw2[(2*kk+1)*64 + n];
    } else if (r < 10240) {
        int t = r - 6144; int kk = t >> 6, n = t & 63;
        lo = uw1[2*kk*64 + n]; hi = uw1[(2*kk+1)*64 + n];
    } else {
        int t = r - 10240; int kk = t >> 6, n = t & 63;
        lo = uw2[2*kk*64 + n]; hi = uw2[(2*kk+1)*64 + n];
    }
    p_w[idx] = bpack(lo, hi);
}

// ---------------------------------------------------------------------------
__global__ void k_zero_cnt(int N) {
    int i = blockIdx.x * blockDim.x + threadIdx.x;
    if (i < N) g_cnt[i] = 0.f;
}
__global__ void k_count(const int* __restrict__ dst, int E) {
    int e = blockIdx.x * blockDim.x + threadIdx.x;
    if (e < E) atomicAdd(&g_cnt[dst[e]], 1.f);
}
__global__ void k_inv(int N) {
    int i = blockIdx.x * blockDim.x + threadIdx.x;
    if (i < N) g_inv[i] = 1.f / fmaxf(g_cnt[i], 1.f);
}

// ---------------------------------------------------------------------------
// pre-phase mma: A = bf16 h pairs at s_u (given stride, offset 0),
// B = W' pairs [32][128]. Warp covers rows m0..m0+15, 128 cols.
// Writes g_as/g_ad bf16 pairs.
// ---------------------------------------------------------------------------
__device__ __forceinline__ void pre_mma(
    const uint* s_u, int stride, const uint* pw,
    int n0, int m0, int qrow, int qcol, int N)
{
    float acc[16][4];
#pragma unroll
    for (int nt = 0; nt < 16; nt++)
#pragma unroll
        for (int c = 0; c < 4; c++) acc[nt][c] = 0.f;

    const uint* Au = s_u + (m0 + qrow) * stride + qcol;
#pragma unroll
    for (int kt = 0; kt < 4; kt++) {
        uint a0 = Au[kt * 8];
        uint a1 = Au[kt * 8 + 8 * stride];
        uint a2 = Au[kt * 8 + 4];
        uint a3 = Au[kt * 8 + 4 + 8 * stride];
        const uint* B0 = pw + (kt * 8 + qcol) * 128 + qrow;
        const uint* B1 = B0 + 4 * 128;
#pragma unroll
        for (int nt = 0; nt < 16; nt++) {
            uint b0 = __ldg(B0 + nt * 8);
            uint b1 = __ldg(B1 + nt * 8);
            mma_bf16(acc[nt][0], acc[nt][1], acc[nt][2], acc[nt][3],
                     a0, a1, a2, a3, b0, b1);
        }
    }
#pragma unroll
    for (int nt = 0; nt < 16; nt++) {
        int col = nt * 8 + qcol * 2;
        uint* base = (col < 64) ? g_as : g_ad;
        int cp = ((col < 64) ? col : col - 64) >> 1;
        int nA = n0 + m0 + qrow;
        int nB = nA + 8;
        if (nA < N) base[(size_t)nA * 32 + cp] = bpack(acc[nt][0], acc[nt][1]);
        if (nB < N) base[(size_t)nB * 32 + cp] = bpack(acc[nt][2], acc[nt][3]);
    }
}

// ---------------------------------------------------------------------------
// encoder (+ fused pre for layer 0): h = mlp2(x) -> g_hb; a_s/a_d; zero g_agg.
// ---------------------------------------------------------------------------
__global__ __launch_bounds__(256) void k_encoder(
    const float* __restrict__ x,
    const float* __restrict__ w1, const float* __restrict__ b1,
    const float* __restrict__ w2, const float* __restrict__ b2, int N)
{
    extern __shared__ float sm[];
    float* s_hid = sm;             // 128 * 65
    float* s_w2  = sm + 128 * 65;  // 64 * 64
    uint*  s_u   = (uint*)sm;      // pre-phase bf16 stage (alias, 128*36)
    __shared__ float s_w1[5 * 64], s_b1[64], s_b2[64];
    __shared__ float s_x[128 * 6];
    int tid = threadIdx.x;
    int n0 = blockIdx.x * 128;

    for (int i = tid; i < 5 * 64; i += 256)  s_w1[i] = w1[i];
    for (int i = tid; i < 64 * 64; i += 256) s_w2[i] = w2[i];
    if (tid < 64) { s_b1[tid] = b1[tid]; s_b2[tid] = b2[tid]; }
    for (int i = tid; i < 128 * 5; i += 256) {
        int r = i / 5, k = i % 5;
        int n = n0 + r;
        s_x[r * 6 + k] = (n < N) ? x[(size_t)n * 5 + k] : 0.f;
    }
#pragma unroll
    for (int i = 0; i < 4; i++) {
        int lin = i * 256 + tid;
        int r = lin >> 3, q = lin & 7;
        int n = n0 + r;
        if (n < N)
            *(uint4*)(g_agg + (size_t)n * 32 + q * 4) = make_uint4(0u, 0u, 0u, 0u);
    }
    __syncthreads();

    int r0 = (tid >> 4) * 8;
    int c0 = (tid & 15) * 4;

    float acc[8][4];
#pragma unroll
    for (int r = 0; r < 8; r++)
#pragma unroll
        for (int c = 0; c < 4; c++) acc[r][c] = 0.f;
#pragma unroll
    for (int k = 0; k < 5; k++) {
        float4 b = *(const float4*)(s_w1 + k * 64 + c0);
#pragma unroll
        for (int r = 0; r < 8; r++) {
            float a = s_x[(r0 + r) * 6 + k];
            acc[r][0] = fmaf(a, b.x, acc[r][0]);
            acc[r][1] = fmaf(a, b.y, acc[r][1]);
            acc[r][2] = fmaf(a, b.z, acc[r][2]);
            acc[r][3] = fmaf(a, b.w, acc[r][3]);
        }
    }
#pragma unroll
    for (int r = 0; r < 8; r++)
#pragma unroll
        for (int c = 0; c < 4; c++)
            s_hid[(r0 + r) * 65 + c0 + c] = fmaxf(acc[r][c] + s_b1[c0 + c], 0.f);
    __syncthreads();

    float acc2[8][4];
#pragma unroll
    for (int r = 0; r < 8; r++)
#pragma unroll
        for (int c = 0; c < 4; c++) acc2[r][c] = 0.f;
#pragma unroll 4
    for (int k = 0; k < 64; k++) {
        float4 b = *(const float4*)(s_w2 + k * 64 + c0);
#pragma unroll
        for (int r = 0; r < 8; r++) {
            float a = s_hid[(r0 + r) * 65 + k];
            acc2[r][0] = fmaf(a, b.x, acc2[r][0]);
            acc2[r][1] = fmaf(a, b.y, acc2[r][1]);
            acc2[r][2] = fmaf(a, b.z, acc2[r][2]);
            acc2[r][3] = fmaf(a, b.w, acc2[r][3]);
        }
    }
    __syncthreads();   // all reads of s_hid/s_w2 done; s_u overwrite safe

    // epilogue: h -> g_hb (bf16 pairs) + s_u
#pragma unroll
    for (int r = 0; r < 8; r++) {
        int n = n0 + r0 + r;
        float vx = fmaxf(acc2[r][0] + s_b2[c0 + 0], 0.f);
        float vy = fmaxf(acc2[r][1] + s_b2[c0 + 1], 0.f);
        float vz = fmaxf(acc2[r][2] + s_b2[c0 + 2], 0.f);
        float vw = fmaxf(acc2[r][3] + s_b2[c0 + 3], 0.f);
        uint plo = bpack(vx, vy), phi = bpack(vz, vw);
        if (n < N) {
            g_hb[(size_t)n * 32 + (c0 >> 1)]     = plo;
            g_hb[(size_t)n * 32 + (c0 >> 1) + 1] = phi;
        }
        s_u[(r0 + r) * 36 + (c0 >> 1)]     = plo;
        s_u[(r0 + r) * 36 + (c0 >> 1) + 1] = phi;
    }
    __syncthreads();

    int warp = tid >> 5, lane = tid & 31;
    pre_mma(s_u, 36, p_w, n0, warp * 16, lane >> 2, lane & 3, N);
}

// ---------------------------------------------------------------------------
// k_edge: 256 threads, 128 edges/block, WARP-LOCAL (one initial barrier only).
// Each warp: 16 edges. Gather+relu -> own smem slab, mma, epilogue, v4 red.
// All __shfl_sync calls are at warp-convergent points.
// ---------------------------------------------------------------------------
__global__ __launch_bounds__(256) void k_edge(
    const int* __restrict__ src, const int* __restrict__ dst,
    const float* __restrict__ b1, int layer,
    const float* __restrict__ b2, int E)
{
    __shared__ uint s_u[128 * 36];
    __shared__ uint s_b1p[32];
    __shared__ float s_b2[64];
    int tid = threadIdx.x;
    int e0 = blockIdx.x * 128;
    const uint* pw = p_w + layer * 12288 + 4096;   // msg w2 pairs [32][64]

    if (tid < 32) s_b1p[tid] = bpack(b1[2 * tid], b1[2 * tid + 1]);
    else if (tid >= 64 && tid < 128) s_b2[tid - 64] = b2[tid - 64];
    __syncthreads();   // the only block barrier

    int warp = tid >> 5, lane = tid & 31;
    int m0 = warp * 16;

    // per-warp edge indices in registers (lanes 0..15)
    int sidx = -1, didx = -1;
    {
        int e = e0 + m0 + lane;
        if (lane < 16 && e < E) { sidx = src[e]; didx = dst[e]; }
    }

    // gather + layer-1: 16 edges x 8 uint4 = 128 tasks / 32 lanes
#pragma unroll
    for (int i = 0; i < 4; i++) {
        int t = i * 32 + lane;
        int el = t >> 3, q = t & 7;
        int s = __shfl_sync(0xffffffffu, sidx, el);   // convergent
        int d = __shfl_sync(0xffffffffu, didx, el);   // convergent
        uint4 v = make_uint4(0u, 0u, 0u, 0u);
        if (s >= 0) {
            uint4 a = __ldg((const uint4*)(g_as + (size_t)s * 32 + q * 4));
            uint4 b = __ldg((const uint4*)(g_ad + (size_t)d * 32 + q * 4));
            v.x = brelu2(badd2(badd2(a.x, b.x), s_b1p[q * 4 + 0]));
            v.y = brelu2(badd2(badd2(a.y, b.y), s_b1p[q * 4 + 1]));
            v.z = brelu2(badd2(badd2(a.z, b.z), s_b1p[q * 4 + 2]));
            v.w = brelu2(badd2(badd2(a.w, b.w), s_b1p[q * 4 + 3]));
        }
        *(uint4*)(s_u + (m0 + el) * 36 + q * 4) = v;
    }
    __syncwarp();

    int qrow = lane >> 2, qcol = lane & 3;

    float acc[8][4];
#pragma unroll
    for (int nt = 0; nt < 8; nt++)
#pragma unroll
        for (int c = 0; c < 4; c++) acc[nt][c] = 0.f;

    const uint* Au = s_u + (m0 + qrow) * 36 + qcol;
#pragma unroll
    for (int kt = 0; kt < 4; kt++) {
        uint a0 = Au[kt * 8];
        uint a1 = Au[kt * 8 + 8 * 36];
        uint a2 = Au[kt * 8 + 4];
        uint a3 = Au[kt * 8 + 4 + 8 * 36];
        const uint* B0 = pw + (kt * 8 + qcol) * 64 + qrow;
        const uint* B1 = B0 + 4 * 64;
#pragma unroll
        for (int nt = 0; nt < 8; nt++) {
            uint b0 = __ldg(B0 + nt * 8);
            uint b1v = __ldg(B1 + nt * 8);
            mma_bf16(acc[nt][0], acc[nt][1], acc[nt][2], acc[nt][3],
                     a0, a1, a2, a3, b0, b1v);
        }
    }
    __syncwarp();

    // epilogue: m = relu(acc + b2) -> own rows
#pragma unroll
    for (int nt = 0; nt < 8; nt++) {
        int c = nt * 8 + qcol * 2;
        float bx = s_b2[c], by = s_b2[c + 1];
        int cp = nt * 4 + qcol;
        s_u[(m0 + qrow) * 36 + cp] =
            bpack(fmaxf(acc[nt][0] + bx, 0.f), fmaxf(acc[nt][1] + by, 0.f));
        s_u[(m0 + qrow + 8) * 36 + cp] =
            bpack(fmaxf(acc[nt][2] + bx, 0.f), fmaxf(acc[nt][3] + by, 0.f));
    }
    __syncwarp();

    // scatter: 16 edges x 8 uint4 vector reds
#pragma unroll
    for (int i = 0; i < 4; i++) {
        int t = i * 32 + lane;
        int el = t >> 3, q = t & 7;
        int d = __shfl_sync(0xffffffffu, didx, el);   // convergent
        if (d >= 0) {
            uint4 v = *(const uint4*)(s_u + (m0 + el) * 36 + q * 4);
            red_v4_bf16(g_agg + (size_t)d * 32 + q * 4, v);
        }
    }
}

// ---------------------------------------------------------------------------
// k_upd: WARP-LOCAL. h = mlp2(concat(h, agg*inv)); zeroes g_agg rows;
// if has_next: fused pre for layer+1; if is_last: fused output head.
// Slab per row (stride 68 uints): [0,32) input / later h pairs, [34,66) hidden.
// ---------------------------------------------------------------------------
__global__ __launch_bounds__(256) void k_upd(
    int layer, const float* __restrict__ b1, const float* __restrict__ b2,
    int has_next,
    const float* __restrict__ ob1, const float* __restrict__ ow2,
    const float* __restrict__ ob2, float* __restrict__ outp, int N)
{
    __shared__ uint s_u[128 * 68];
    __shared__ float s_b1[64], s_b2[64];
    __shared__ float s_ob1[64], s_ow2[192], s_ob2[3];
    int tid = threadIdx.x;
    int n0 = blockIdx.x * 128;
    int is_last = !has_next;
    const uint* pw1 = p_w + layer * 12288 + 6144;
    const uint* pw2 = p_w + layer * 12288 + 10240;

    if (tid < 64) { s_b1[tid] = b1[tid]; s_b2[tid] = b2[tid]; }
    if (is_last) {
        if (tid >= 64 && tid < 128) s_ob1[tid - 64] = ob1[tid - 64];
        if (tid >= 128 && tid < 224) {
            s_ow2[tid - 128] = ow2[tid - 128];
            s_ow2[tid - 128 + 96] = ow2[tid - 128 + 96];
        }
        if (tid >= 224 && tid < 227) s_ob2[tid - 224] = ob2[tid - 224];
    }
    __syncthreads();   // the only block barrier

    int warp = tid >> 5, lane = tid & 31;
    int m0 = warp * 16;

    float ivreg = 1.f;
    if (lane < 16) {
        int n = n0 + m0 + lane;
        if (n < N) ivreg = __ldg(g_inv + n);
    }

    // stage concat(h, agg*inv): 16 rows x 16 uint4 = 256 tasks / 32 lanes.
    // NOTE: the shfl broadcast is hoisted to a convergent point (R10 hang fix).
#pragma unroll
    for (int i = 0; i < 8; i++) {
        int t = i * 32 + lane;
        int rl = t >> 4, q = t & 15;
        float iv = __shfl_sync(0xffffffffu, ivreg, rl);   // convergent
        int n = n0 + m0 + rl;
        uint4 v = make_uint4(0u, 0u, 0u, 0u);
        if (n < N) {
            if (q < 8) {
                v = *(const uint4*)(g_hb + (size_t)n * 32 + q * 4);
            } else {
                int qq = q - 8;
                uint4 a = *(const uint4*)(g_agg + (size_t)n * 32 + qq * 4);
                float2 p0 = bunpack(a.x), p1 = bunpack(a.y);
                float2 p2 = bunpack(a.z), p3 = bunpack(a.w);
                v.x = bpack(p0.x * iv, p0.y * iv);
                v.y = bpack(p1.x * iv, p1.y * iv);
                v.z = bpack(p2.x * iv, p2.y * iv);
                v.w = bpack(p3.x * iv, p3.y * iv);
                *(uint4*)(g_agg + (size_t)n * 32 + qq * 4) = make_uint4(0u, 0u, 0u, 0u);
            }
        }
        *(uint4*)(s_u + (m0 + rl) * 68 + q * 4) = v;
    }
    __syncwarp();

    int qrow = lane >> 2, qcol = lane & 3;

    // phase 1: K=128
    float acc[8][4];
#pragma unroll
    for (int nt = 0; nt < 8; nt++)
#pragma unroll
        for (int c = 0; c < 4; c++) acc[nt][c] = 0.f;
    {
        const uint* Au = s_u + (m0 + qrow) * 68 + qcol;
#pragma unroll
        for (int kt = 0; kt < 8; kt++) {
            uint a0 = Au[kt * 8];
            uint a1 = Au[kt * 8 + 8 * 68];
            uint a2 = Au[kt * 8 + 4];
            uint a3 = Au[kt * 8 + 4 + 8 * 68];
            const uint* B0 = pw1 + (kt * 8 + qcol) * 64 + qrow;
            const uint* B1 = B0 + 4 * 64;
#pragma unroll
            for (int nt = 0; nt < 8; nt++) {
                uint b0 = __ldg(B0 + nt * 8);
                uint b1v = __ldg(B1 + nt * 8);
                mma_bf16(acc[nt][0], acc[nt][1], acc[nt][2], acc[nt][3],
                         a0, a1, a2, a3, b0, b1v);
            }
        }
    }
    __syncwarp();

    // hidden = relu(acc + b1) -> slab offset 34
#pragma unroll
    for (int nt = 0; nt < 8; nt++) {
        int c = nt * 8 + qcol * 2;
        float bx = s_b1[c], by = s_b1[c + 1];
        int cp = 34 + nt * 4 + qcol;
        s_u[(m0 + qrow) * 68 + cp] =
            bpack(fmaxf(acc[nt][0] + bx, 0.f), fmaxf(acc[nt][1] + by, 0.f));
        s_u[(m0 + qrow + 8) * 68 + cp] =
            bpack(fmaxf(acc[nt][2] + bx, 0.f), fmaxf(acc[nt][3] + by, 0.f));
    }
    __syncwarp();

    // phase 2: K=64 (hidden at offset 34)
    float acc2[8][4];
#pragma unroll
    for (int nt = 0; nt < 8; nt++)
#pragma unroll
        for (int c = 0; c < 4; c++) acc2[nt][c] = 0.f;
    {
        const uint* Au = s_u + (m0 + qrow) * 68 + 34 + qcol;
#pragma unroll
        for (int kt = 0; kt < 4; kt++) {
            uint a0 = Au[kt * 8];
            uint a1 = Au[kt * 8 + 8 * 68];
            uint a2 = Au[kt * 8 + 4];
            uint a3 = Au[kt * 8 + 4 + 8 * 68];
            const uint* B0 = pw2 + (kt * 8 + qcol) * 64 + qrow;
            const uint* B1 = B0 + 4 * 64;
#pragma unroll
            for (int nt = 0; nt < 8; nt++) {
                uint b0 = __ldg(B0 + nt * 8);
                uint b1v = __ldg(B1 + nt * 8);
                mma_bf16(acc2[nt][0], acc2[nt][1], acc2[nt][2], acc2[nt][3],
                         a0, a1, a2, a3, b0, b1v);
            }
        }
    }
    __syncwarp();

    // h = relu(acc2 + b2) -> slab offset 0 (bf16) + g_hb (if not last)
#pragma unroll
    for (int nt = 0; nt < 8; nt++) {
        int c = nt * 8 + qcol * 2;
        float bx = s_b2[c], by = s_b2[c + 1];
        int cp = nt * 4 + qcol;
        int nA = n0 + m0 + qrow;
        int nB = nA + 8;
        uint pA = bpack(fmaxf(acc2[nt][0] + bx, 0.f), fmaxf(acc2[nt][1] + by, 0.f));
        uint pB = bpack(fmaxf(acc2[nt][2] + bx, 0.f), fmaxf(acc2[nt][3] + by, 0.f));
        s_u[(m0 + qrow) * 68 + cp]     = pA;
        s_u[(m0 + qrow + 8) * 68 + cp] = pB;
        if (!is_last) {
            if (nA < N) g_hb[(size_t)nA * 32 + cp] = pA;
            if (nB < N) g_hb[(size_t)nB * 32 + cp] = pB;
        }
    }
    __syncwarp();

    if (has_next) {
        pre_mma(s_u, 68, p_w + (layer + 1) * 12288, n0, m0, qrow, qcol, N);
        return;
    }

    // ---- fused output head (is_last) ----
    // phase 3: hidden2 = relu(h @ ow1 + ob1), h pairs at slab offset 0
    const uint* pw3 = p_w + 3 * 12288;
    float acc3[8][4];
#pragma unroll
    for (int nt = 0; nt < 8; nt++)
#pragma unroll
        for (int c = 0; c < 4; c++) acc3[nt][c] = 0.f;
    {
        const uint* Au = s_u + (m0 + qrow) * 68 + qcol;
#pragma unroll
        for (int kt = 0; kt < 4; kt++) {
            uint a0 = Au[kt * 8];
            uint a1 = Au[kt * 8 + 8 * 68];
            uint a2 = Au[kt * 8 + 4];
            uint a3 = Au[kt * 8 + 4 + 8 * 68];
            const uint* B0 = pw3 + (kt * 8 + qcol) * 64 + qrow;
            const uint* B1 = B0 + 4 * 64;
#pragma unroll
            for (int nt = 0; nt < 8; nt++) {
                uint b0 = __ldg(B0 + nt * 8);
                uint b1v = __ldg(B1 + nt * 8);
                mma_bf16(acc3[nt][0], acc3[nt][1], acc3[nt][2], acc3[nt][3],
                         a0, a1, a2, a3, b0, b1v);
            }
        }
    }

    // partial dots with ow2 [64][3] over this lane's 16 cols, rows A/B
    float pA[3] = {0.f, 0.f, 0.f}, pB[3] = {0.f, 0.f, 0.f};
#pragma unroll
    for (int nt = 0; nt < 8; nt++) {
        int c = nt * 8 + qcol * 2;
        float o1a = s_ob1[c], o1b = s_ob1[c + 1];
        float hA0 = fmaxf(acc3[nt][0] + o1a, 0.f);
        float hA1 = fmaxf(acc3[nt][1] + o1b, 0.f);
        float hB0 = fmaxf(acc3[nt][2] + o1a, 0.f);
        float hB1 = fmaxf(acc3[nt][3] + o1b, 0.f);
#pragma unroll
        for (int cc = 0; cc < 3; cc++) {
            float w0 = s_ow2[c * 3 + cc], w1v = s_ow2[(c + 1) * 3 + cc];
            pA[cc] = fmaf(hA0, w0, fmaf(hA1, w1v, pA[cc]));
            pB[cc] = fmaf(hB0, w0, fmaf(hB1, w1v, pB[cc]));
        }
    }
    // butterfly reduce over qcol (lanes differing in bits 0,1) — convergent
#pragma unroll
    for (int cc = 0; cc < 3; cc++) {
        pA[cc] += __shfl_xor_sync(0xffffffffu, pA[cc], 1);
        pA[cc] += __shfl_xor_sync(0xffffffffu, pA[cc], 2);
        pB[cc] += __shfl_xor_sync(0xffffffffu, pB[cc], 1);
        pB[cc] += __shfl_xor_sync(0xffffffffu, pB[cc], 2);
    }
    if (qcol == 0) {
        int nA = n0 + m0 + qrow;
        int nB = nA + 8;
        if (nA < N) {
#pragma unroll
            for (int cc = 0; cc < 3; cc++)
                outp[(size_t)nA * 3 + cc] =
                    6.283185307179586f / (1.f + expf(-(pA[cc] + s_ob2[cc])));
        }
        if (nB < N) {
#pragma unroll
            for (int cc = 0; cc < 3; cc++)
                outp[(size_t)nB * 3 + cc] =
                    6.283185307179586f / (1.f + expf(-(pB[cc] + s_ob2[cc])));
        }
    }
}

// ---------------------------------------------------------------------------
extern "C" void kernel_launch(void* const* d_in, const int* in_sizes, int n_in,
                              void* d_out, int out_size)
{
    const float* x      = (const float*)d_in[0];
    const int*   ei     = (const int*)  d_in[1];
    const float* enc_w1 = (const float*)d_in[2];
    const float* enc_b1 = (const float*)d_in[3];
    const float* enc_w2 = (const float*)d_in[4];
    const float* enc_b2 = (const float*)d_in[5];
    const float* msg_w1 = (const float*)d_in[6];
    const float* msg_b1 = (const float*)d_in[7];
    const float* msg_w2 = (const float*)d_in[8];
    const float* msg_b2 = (const float*)d_in[9];
    const float* upd_w1 = (const float*)d_in[10];
    const float* upd_b1 = (const float*)d_in[11];
    const float* upd_w2 = (const float*)d_in[12];
    const float* upd_b2 = (const float*)d_in[13];
    const float* out_w1 = (const float*)d_in[14];
    const float* out_b1 = (const float*)d_in[15];
    const float* out_w2 = (const float*)d_in[16];
    const float* out_b2 = (const float*)d_in[17];

    int N = in_sizes[0] / 5;
    int E = in_sizes[1] / 2;
    if (N > NMAX) N = NMAX;
    if (E > EMAX) E = EMAX;
    const int* src = ei;
    const int* dstp = ei + E;

    const int ENC_SM = (128 * 65 + 64 * 64) * 4;    // 49664
    cudaFuncSetAttribute(k_encoder, cudaFuncAttributeMaxDynamicSharedMemorySize, ENC_SM);

    int nbN256 = (N + 255) / 256;
    int nbE256 = (E + 255) / 256;
    int nbN128 = (N + 127) / 128;
    int nbE128 = (E + 127) / 128;

    k_pack<<<(3 * 12288 + 2048 + 255) / 256, 256>>>(msg_w1, msg_w2, upd_w1,
                                                    upd_w2, out_w1);
    k_zero_cnt<<<nbN256, 256>>>(N);
    k_count<<<nbE256, 256>>>(dstp, E);
    k_inv<<<nbN256, 256>>>(N);
    k_encoder<<<nbN128, 256, ENC_SM>>>(x, enc_w1, enc_b1, enc_w2, enc_b2, N);

    for (int l = 0; l < 3; l++) {
        k_edge<<<nbE128, 256>>>(src, dstp, msg_b1 + l * 64, l,
                                msg_b2 + l * 64, E);
        k_upd<<<nbN128, 256>>>(l, upd_b1 + l * 64, upd_b2 + l * 64,
                               (l < 2) ? 1 : 0,
                               out_b1, out_w2, out_b2, (float*)d_out, N);
    }
}

// round 12
// speedup vs baseline: 3.2278x; 1.0043x over previous
#include <cuda_runtime.h>
#include <cuda_bf16.h>

// ---------------------------------------------------------------------------
// FixedSimpleGNN: 3-layer MPNN, N=100000, E=1000000, H=64.
//   - per-node a_s/a_d (factorized msg layer-1, bias folded into a_s)
//   - per-edge bf16 mma.m16n8k16 msg layer-2, warp-local
//   - v4.bf16x2 red scatter
//   - warp-local bf16 mma update MLP; output head fused into last update
//   - weights packed lane-contiguous: B-frags loaded as uint4 (4x fewer LDG)
// ---------------------------------------------------------------------------

#define NMAX 100000
#define EMAX 1000000
#define PACKN (3 * 12288 + 2048)

typedef unsigned int uint;

__device__ uint  g_hb [NMAX * 32];   // h, bf16x2 pairs
__device__ uint  g_as [NMAX * 32];   // bf16x2 pairs (msg_b1 folded in)
__device__ uint  g_ad [NMAX * 32];   // bf16x2 pairs
__device__ uint  g_agg[NMAX * 32];   // bf16x2 pairs (atomic accum)
__device__ float g_cnt[NMAX];

// packed bf16x2 weights in lane-contiguous B-fragment-v4 layout:
//   addr(kt,half,qc,qr,ntv; Ncols) = ((kt*2+half)*4+qc)*(8*Ncols/8) + qr*(Ncols/8) + ntv
//   value = pair( W[2*kp][n], W[2*kp+1][n] ), kp = kt*8+half*4+qc, n = ntv*8+qr
// per layer (12288 uints):
//   +0:     msg W'  (K=64, N=128)  4096
//   +4096:  msg w2  (K=64, N=64)   2048
//   +6144:  upd w1  (K=128,N=64)   4096
//   +10240: upd w2  (K=64, N=64)   2048
// +36864: out w1 (K=64,N=64) 2048
__device__ uint p_w[PACKN];

__device__ __forceinline__ uint bpack(float lo, float hi) {
    __nv_bfloat162 p = __floats2bfloat162_rn(lo, hi);
    return *(uint*)&p;
}
__device__ __forceinline__ float2 bunpack(uint v) {
    return __bfloat1622float2(*(__nv_bfloat162*)&v);
}
__device__ __forceinline__ uint badd2(uint a, uint b) {
    __nv_bfloat162 r = __hadd2(*(__nv_bfloat162*)&a, *(__nv_bfloat162*)&b);
    return *(uint*)&r;
}
__device__ __forceinline__ uint brelu2(uint a) {
    __nv_bfloat162 z = __float2bfloat162_rn(0.f);
    __nv_bfloat162 r = __hmax2(*(__nv_bfloat162*)&a, z);
    return *(uint*)&r;
}
__device__ __forceinline__ void mma_bf16(
    float& c0, float& c1, float& c2, float& c3,
    uint a0, uint a1, uint a2, uint a3, uint b0, uint b1)
{
    asm volatile(
        "mma.sync.aligned.m16n8k16.row.col.f32.bf16.bf16.f32 "
        "{%0,%1,%2,%3}, {%4,%5,%6,%7}, {%8,%9}, {%0,%1,%2,%3};"
        : "+f"(c0), "+f"(c1), "+f"(c2), "+f"(c3)
        : "r"(a0), "r"(a1), "r"(a2), "r"(a3), "r"(b0), "r"(b1));
}
__device__ __forceinline__ void red_v4_bf16(uint* addr, uint4 v) {
    asm volatile(
        "red.global.add.noftz.v4.bf16x2 [%0], {%1,%2,%3,%4};"
        :: "l"(addr), "r"(v.x), "r"(v.y), "r"(v.z), "r"(v.w) : "memory");
}

// ---------------------------------------------------------------------------
// k_pack: build lane-contiguous bf16x2 weight arrays; also zeroes g_cnt.
// ---------------------------------------------------------------------------
__global__ void k_pack(const float* __restrict__ msg_w1,
                       const float* __restrict__ msg_w2,
                       const float* __restrict__ upd_w1,
                       const float* __restrict__ upd_w2,
                       const float* __restrict__ out_w1, int N)
{
    int idx = blockIdx.x * blockDim.x + threadIdx.x;
    if (idx >= PACKN) {
        int i = idx - PACKN;
        if (i < N) g_cnt[i] = 0.f;
        return;
    }
    const float* W;
    int r, Ncols = 64;
    bool concat = false;
    if (idx >= 3 * 12288) {
        r = idx - 3 * 12288; W = out_w1;
    } else {
        int l = idx / 12288; r = idx % 12288;
        if (r < 4096)       { W = msg_w1 + l * 8192; Ncols = 128; concat = true; }
        else if (r < 6144)  { r -= 4096;  W = msg_w2 + l * 4096; }
        else if (r < 10240) { r -= 6144;  W = upd_w1 + l * 8192; }
        else                { r -= 10240; W = upd_w2 + l * 4096; }
    }
    int nv = Ncols >> 3;
    int ntv = r % nv; int t = r / nv;
    int qr = t & 7; t >>= 3;
    int qc = t & 3; t >>= 2;
    int half = t & 1; int kt = t >> 1;
    int kp = kt * 8 + half * 4 + qc;
    int n = ntv * 8 + qr;
    float lo, hi;
    if (concat) {
        if (n < 64) { lo = W[(2*kp)*64 + n];           hi = W[(2*kp+1)*64 + n]; }
        else        { lo = W[(64+2*kp)*64 + (n-64)];   hi = W[(64+2*kp+1)*64 + (n-64)]; }
    } else {
        lo = W[(2*kp)*64 + n]; hi = W[(2*kp+1)*64 + n];
    }
    p_w[idx] = bpack(lo, hi);
}

// ---------------------------------------------------------------------------
__global__ void k_count(const int* __restrict__ dst, int E) {
    int e = blockIdx.x * blockDim.x + threadIdx.x;
    if (e < E) atomicAdd(&g_cnt[dst[e]], 1.f);
}

// ---------------------------------------------------------------------------
// pre-phase mma: A = bf16 h pairs in s_u (offset 0, given stride),
// B = W' (K=64, N=128) packed. Warp covers rows m0..m0+15, 128 cols.
// msg_b1 of the target layer is folded into the a_s half.
// ---------------------------------------------------------------------------
__device__ __forceinline__ void pre_mma(
    const uint* s_u, int stride, const uint* pw, const float* __restrict__ b1g,
    int n0, int m0, int qrow, int qcol, int N)
{
    float acc[16][4];
#pragma unroll
    for (int nt = 0; nt < 16; nt++)
#pragma unroll
        for (int c = 0; c < 4; c++) acc[nt][c] = 0.f;

    const uint* Au = s_u + (m0 + qrow) * stride + qcol;
#pragma unroll
    for (int kt = 0; kt < 4; kt++) {
        uint a0 = Au[kt * 8];
        uint a1 = Au[kt * 8 + 8 * stride];
        uint a2 = Au[kt * 8 + 4];
        uint a3 = Au[kt * 8 + 4 + 8 * stride];
        const uint* p0 = pw + ((kt * 2 + 0) * 4 + qcol) * 128 + qrow * 16;
        const uint* p1 = pw + ((kt * 2 + 1) * 4 + qcol) * 128 + qrow * 16;
#pragma unroll
        for (int hh = 0; hh < 2; hh++) {
            uint B0[8], B1[8];
            *(uint4*)&B0[0] = __ldg((const uint4*)(p0 + hh * 8));
            *(uint4*)&B0[4] = __ldg((const uint4*)(p0 + hh * 8 + 4));
            *(uint4*)&B1[0] = __ldg((const uint4*)(p1 + hh * 8));
            *(uint4*)&B1[4] = __ldg((const uint4*)(p1 + hh * 8 + 4));
#pragma unroll
            for (int nt = 0; nt < 8; nt++) {
                int a = hh * 8 + nt;
                mma_bf16(acc[a][0], acc[a][1], acc[a][2], acc[a][3],
                         a0, a1, a2, a3, B0[nt], B1[nt]);
            }
        }
    }
#pragma unroll
    for (int nt = 0; nt < 16; nt++) {
        int col = nt * 8 + qcol * 2;
        int nA = n0 + m0 + qrow;
        int nB = nA + 8;
        if (col < 64) {
            float bx = __ldg(b1g + col), by = __ldg(b1g + col + 1);
            if (nA < N) g_as[(size_t)nA * 32 + (col >> 1)] =
                bpack(acc[nt][0] + bx, acc[nt][1] + by);
            if (nB < N) g_as[(size_t)nB * 32 + (col >> 1)] =
                bpack(acc[nt][2] + bx, acc[nt][3] + by);
        } else {
            int cp = (col - 64) >> 1;
            if (nA < N) g_ad[(size_t)nA * 32 + cp] = bpack(acc[nt][0], acc[nt][1]);
            if (nB < N) g_ad[(size_t)nB * 32 + cp] = bpack(acc[nt][2], acc[nt][3]);
        }
    }
}

// ---------------------------------------------------------------------------
// encoder (+ fused pre for layer 0): h = mlp2(x) -> g_hb; a_s/a_d; zero g_agg.
// ---------------------------------------------------------------------------
__global__ __launch_bounds__(256) void k_encoder(
    const float* __restrict__ x,
    const float* __restrict__ w1, const float* __restrict__ b1,
    const float* __restrict__ w2, const float* __restrict__ b2,
    const float* __restrict__ msg_b1_0, int N)
{
    extern __shared__ float sm[];
    float* s_hid = sm;             // 128 * 65
    float* s_w2  = sm + 128 * 65;  // 64 * 64
    uint*  s_u   = (uint*)sm;      // pre-phase bf16 stage (alias, 128*36)
    __shared__ float s_w1[5 * 64], s_b1[64], s_b2[64];
    __shared__ float s_x[128 * 6];
    int tid = threadIdx.x;
    int n0 = blockIdx.x * 128;

    for (int i = tid; i < 5 * 64; i += 256)  s_w1[i] = w1[i];
    for (int i = tid; i < 64 * 64; i += 256) s_w2[i] = w2[i];
    if (tid < 64) { s_b1[tid] = b1[tid]; s_b2[tid] = b2[tid]; }
    for (int i = tid; i < 128 * 5; i += 256) {
        int r = i / 5, k = i % 5;
        int n = n0 + r;
        s_x[r * 6 + k] = (n < N) ? x[(size_t)n * 5 + k] : 0.f;
    }
#pragma unroll
    for (int i = 0; i < 4; i++) {
        int lin = i * 256 + tid;
        int r = lin >> 3, q = lin & 7;
        int n = n0 + r;
        if (n < N)
            *(uint4*)(g_agg + (size_t)n * 32 + q * 4) = make_uint4(0u, 0u, 0u, 0u);
    }
    __syncthreads();

    int r0 = (tid >> 4) * 8;
    int c0 = (tid & 15) * 4;

    float acc[8][4];
#pragma unroll
    for (int r = 0; r < 8; r++)
#pragma unroll
        for (int c = 0; c < 4; c++) acc[r][c] = 0.f;
#pragma unroll
    for (int k = 0; k < 5; k++) {
        float4 b = *(const float4*)(s_w1 + k * 64 + c0);
#pragma unroll
        for (int r = 0; r < 8; r++) {
            float a = s_x[(r0 + r) * 6 + k];
            acc[r][0] = fmaf(a, b.x, acc[r][0]);
            acc[r][1] = fmaf(a, b.y, acc[r][1]);
            acc[r][2] = fmaf(a, b.z, acc[r][2]);
            acc[r][3] = fmaf(a, b.w, acc[r][3]);
        }
    }
#pragma unroll
    for (int r = 0; r < 8; r++)
#pragma unroll
        for (int c = 0; c < 4; c++)
            s_hid[(r0 + r) * 65 + c0 + c] = fmaxf(acc[r][c] + s_b1[c0 + c], 0.f);
    __syncthreads();

    float acc2[8][4];
#pragma unroll
    for (int r = 0; r < 8; r++)
#pragma unroll
        for (int c = 0; c < 4; c++) acc2[r][c] = 0.f;
#pragma unroll 4
    for (int k = 0; k < 64; k++) {
        float4 b = *(const float4*)(s_w2 + k * 64 + c0);
#pragma unroll
        for (int r = 0; r < 8; r++) {
            float a = s_hid[(r0 + r) * 65 + k];
            acc2[r][0] = fmaf(a, b.x, acc2[r][0]);
            acc2[r][1] = fmaf(a, b.y, acc2[r][1]);
            acc2[r][2] = fmaf(a, b.z, acc2[r][2]);
            acc2[r][3] = fmaf(a, b.w, acc2[r][3]);
        }
    }
    __syncthreads();   // all reads of s_hid/s_w2 done; s_u overwrite safe

    // epilogue: h -> g_hb (bf16 pairs) + s_u
#pragma unroll
    for (int r = 0; r < 8; r++) {
        int n = n0 + r0 + r;
        float vx = fmaxf(acc2[r][0] + s_b2[c0 + 0], 0.f);
        float vy = fmaxf(acc2[r][1] + s_b2[c0 + 1], 0.f);
        float vz = fmaxf(acc2[r][2] + s_b2[c0 + 2], 0.f);
        float vw = fmaxf(acc2[r][3] + s_b2[c0 + 3], 0.f);
        uint plo = bpack(vx, vy), phi = bpack(vz, vw);
        if (n < N) {
            g_hb[(size_t)n * 32 + (c0 >> 1)]     = plo;
            g_hb[(size_t)n * 32 + (c0 >> 1) + 1] = phi;
        }
        s_u[(r0 + r) * 36 + (c0 >> 1)]     = plo;
        s_u[(r0 + r) * 36 + (c0 >> 1) + 1] = phi;
    }
    __syncthreads();

    int warp = tid >> 5, lane = tid & 31;
    pre_mma(s_u, 36, p_w, msg_b1_0, n0, warp * 16, lane >> 2, lane & 3, N);
}

// ---------------------------------------------------------------------------
// k_edge: 256 threads, 128 edges/block, warp-local.
// hidden = relu(a_s[src] + a_d[dst]) (bias pre-folded into a_s).
// ---------------------------------------------------------------------------
__global__ __launch_bounds__(256) void k_edge(
    const int* __restrict__ src, const int* __restrict__ dst,
    int layer, const float* __restrict__ b2, int E)
{
    __shared__ uint s_u[128 * 36];
    __shared__ float s_b2[64];
    int tid = threadIdx.x;
    int e0 = blockIdx.x * 128;
    const uint* pw = p_w + layer * 12288 + 4096;   // msg w2 packed (K=64,N=64)

    if (tid < 64) s_b2[tid] = b2[tid];
    __syncthreads();   // the only block barrier

    int warp = tid >> 5, lane = tid & 31;
    int m0 = warp * 16;

    int sidx = -1, didx = -1;
    {
        int e = e0 + m0 + lane;
        if (lane < 16 && e < E) { sidx = src[e]; didx = dst[e]; }
    }

    // gather + layer-1: 16 edges x 8 uint4 = 128 tasks / 32 lanes
#pragma unroll
    for (int i = 0; i < 4; i++) {
        int t = i * 32 + lane;
        int el = t >> 3, q = t & 7;
        int s = __shfl_sync(0xffffffffu, sidx, el);   // convergent
        int d = __shfl_sync(0xffffffffu, didx, el);   // convergent
        uint4 v = make_uint4(0u, 0u, 0u, 0u);
        if (s >= 0) {
            uint4 a = __ldg((const uint4*)(g_as + (size_t)s * 32 + q * 4));
            uint4 b = __ldg((const uint4*)(g_ad + (size_t)d * 32 + q * 4));
            v.x = brelu2(badd2(a.x, b.x));
            v.y = brelu2(badd2(a.y, b.y));
            v.z = brelu2(badd2(a.z, b.z));
            v.w = brelu2(badd2(a.w, b.w));
        }
        *(uint4*)(s_u + (m0 + el) * 36 + q * 4) = v;
    }
    __syncwarp();

    int qrow = lane >> 2, qcol = lane & 3;

    float acc[8][4];
#pragma unroll
    for (int nt = 0; nt < 8; nt++)
#pragma unroll
        for (int c = 0; c < 4; c++) acc[nt][c] = 0.f;

    const uint* Au = s_u + (m0 + qrow) * 36 + qcol;
#pragma unroll
    for (int kt = 0; kt < 4; kt++) {
        uint a0 = Au[kt * 8];
        uint a1 = Au[kt * 8 + 8 * 36];
        uint a2 = Au[kt * 8 + 4];
        uint a3 = Au[kt * 8 + 4 + 8 * 36];
        const uint* p0 = pw + ((kt * 2 + 0) * 4 + qcol) * 64 + qrow * 8;
        const uint* p1 = pw + ((kt * 2 + 1) * 4 + qcol) * 64 + qrow * 8;
        uint B0[8], B1[8];
        *(uint4*)&B0[0] = __ldg((const uint4*)p0);
        *(uint4*)&B0[4] = __ldg((const uint4*)(p0 + 4));
        *(uint4*)&B1[0] = __ldg((const uint4*)p1);
        *(uint4*)&B1[4] = __ldg((const uint4*)(p1 + 4));
#pragma unroll
        for (int nt = 0; nt < 8; nt++)
            mma_bf16(acc[nt][0], acc[nt][1], acc[nt][2], acc[nt][3],
                     a0, a1, a2, a3, B0[nt], B1[nt]);
    }
    __syncwarp();

    // epilogue: m = relu(acc + b2) -> own rows
#pragma unroll
    for (int nt = 0; nt < 8; nt++) {
        int c = nt * 8 + qcol * 2;
        float bx = s_b2[c], by = s_b2[c + 1];
        int cp = nt * 4 + qcol;
        s_u[(m0 + qrow) * 36 + cp] =
            bpack(fmaxf(acc[nt][0] + bx, 0.f), fmaxf(acc[nt][1] + by, 0.f));
        s_u[(m0 + qrow + 8) * 36 + cp] =
            bpack(fmaxf(acc[nt][2] + bx, 0.f), fmaxf(acc[nt][3] + by, 0.f));
    }
    __syncwarp();

    // scatter: 16 edges x 8 uint4 vector reds
#pragma unroll
    for (int i = 0; i < 4; i++) {
        int t = i * 32 + lane;
        int el = t >> 3, q = t & 7;
        int d = __shfl_sync(0xffffffffu, didx, el);   // convergent
        if (d >= 0) {
            uint4 v = *(const uint4*)(s_u + (m0 + el) * 36 + q * 4);
            red_v4_bf16(g_agg + (size_t)d * 32 + q * 4, v);
        }
    }
}

// ---------------------------------------------------------------------------
// k_upd: warp-local. h = mlp2(concat(h, agg/deg)); zeroes g_agg rows;
// if has_next: fused pre for layer+1; else: fused output head.
// Slab per row (stride 68 uints): [0,32) input / later h pairs, [34,66) hidden.
// ---------------------------------------------------------------------------
__global__ __launch_bounds__(256) void k_upd(
    int layer, const float* __restrict__ b1, const float* __restrict__ b2,
    int has_next, const float* __restrict__ msg_b1_next,
    const float* __restrict__ ob1, const float* __restrict__ ow2,
    const float* __restrict__ ob2, float* __restrict__ outp, int N)
{
    __shared__ uint s_u[128 * 68];
    __shared__ float s_b1[64], s_b2[64];
    __shared__ float s_ob1[64], s_ow2[192], s_ob2[3];
    int tid = threadIdx.x;
    int n0 = blockIdx.x * 128;
    int is_last = !has_next;
    const uint* pw1 = p_w + layer * 12288 + 6144;    // upd w1 packed (K=128,N=64)
    const uint* pw2 = p_w + layer * 12288 + 10240;   // upd w2 packed (K=64,N=64)

    if (tid < 64) { s_b1[tid] = b1[tid]; s_b2[tid] = b2[tid]; }
    if (is_last) {
        if (tid >= 64 && tid < 128) s_ob1[tid - 64] = ob1[tid - 64];
        if (tid >= 128 && tid < 224) {
            s_ow2[tid - 128] = ow2[tid - 128];
            s_ow2[tid - 128 + 96] = ow2[tid - 128 + 96];
        }
        if (tid >= 224 && tid < 227) s_ob2[tid - 224] = ob2[tid - 224];
    }
    __syncthreads();   // the only block barrier

    int warp = tid >> 5, lane = tid & 31;
    int m0 = warp * 16;

    float ivreg = 1.f;
    if (lane < 16) {
        int n = n0 + m0 + lane;
        if (n < N) ivreg = 1.f / fmaxf(__ldg(g_cnt + n), 1.f);
    }

    // stage concat(h, agg*iv): 16 rows x 16 uint4 (shfl hoisted = convergent)
#pragma unroll
    for (int i = 0; i < 8; i++) {
        int t = i * 32 + lane;
        int rl = t >> 4, q = t & 15;
        float iv = __shfl_sync(0xffffffffu, ivreg, rl);   // convergent
        int n = n0 + m0 + rl;
        uint4 v = make_uint4(0u, 0u, 0u, 0u);
        if (n < N) {
            if (q < 8) {
                v = *(const uint4*)(g_hb + (size_t)n * 32 + q * 4);
            } else {
                int qq = q - 8;
                uint4 a = *(const uint4*)(g_agg + (size_t)n * 32 + qq * 4);
                float2 p0 = bunpack(a.x), p1 = bunpack(a.y);
                float2 p2 = bunpack(a.z), p3 = bunpack(a.w);
                v.x = bpack(p0.x * iv, p0.y * iv);
                v.y = bpack(p1.x * iv, p1.y * iv);
                v.z = bpack(p2.x * iv, p2.y * iv);
                v.w = bpack(p3.x * iv, p3.y * iv);
                *(uint4*)(g_agg + (size_t)n * 32 + qq * 4) = make_uint4(0u, 0u, 0u, 0u);
            }
        }
        *(uint4*)(s_u + (m0 + rl) * 68 + q * 4) = v;
    }
    __syncwarp();

    int qrow = lane >> 2, qcol = lane & 3;

    // phase 1: K=128
    float acc[8][4];
#pragma unroll
    for (int nt = 0; nt < 8; nt++)
#pragma unroll
        for (int c = 0; c < 4; c++) acc[nt][c] = 0.f;
    {
        const uint* Au = s_u + (m0 + qrow) * 68 + qcol;
#pragma unroll
        for (int kt = 0; kt < 8; kt++) {
            uint a0 = Au[kt * 8];
            uint a1 = Au[kt * 8 + 8 * 68];
            uint a2 = Au[kt * 8 + 4];
            uint a3 = Au[kt * 8 + 4 + 8 * 68];
            const uint* p0 = pw1 + ((kt * 2 + 0) * 4 + qcol) * 64 + qrow * 8;
            const uint* p1 = pw1 + ((kt * 2 + 1) * 4 + qcol) * 64 + qrow * 8;
            uint B0[8], B1[8];
            *(uint4*)&B0[0] = __ldg((const uint4*)p0);
            *(uint4*)&B0[4] = __ldg((const uint4*)(p0 + 4));
            *(uint4*)&B1[0] = __ldg((const uint4*)p1);
            *(uint4*)&B1[4] = __ldg((const uint4*)(p1 + 4));
#pragma unroll
            for (int nt = 0; nt < 8; nt++)
                mma_bf16(acc[nt][0], acc[nt][1], acc[nt][2], acc[nt][3],
                         a0, a1, a2, a3, B0[nt], B1[nt]);
        }
    }
    __syncwarp();

    // hidden = relu(acc + b1) -> slab offset 34
#pragma unroll
    for (int nt = 0; nt < 8; nt++) {
        int c = nt * 8 + qcol * 2;
        float bx = s_b1[c], by = s_b1[c + 1];
        int cp = 34 + nt * 4 + qcol;
        s_u[(m0 + qrow) * 68 + cp] =
            bpack(fmaxf(acc[nt][0] + bx, 0.f), fmaxf(acc[nt][1] + by, 0.f));
        s_u[(m0 + qrow + 8) * 68 + cp] =
            bpack(fmaxf(acc[nt][2] + bx, 0.f), fmaxf(acc[nt][3] + by, 0.f));
    }
    __syncwarp();

    // phase 2: K=64 (hidden at offset 34)
    float acc2[8][4];
#pragma unroll
    for (int nt = 0; nt < 8; nt++)
#pragma unroll
        for (int c = 0; c < 4; c++) acc2[nt][c] = 0.f;
    {
        const uint* Au = s_u + (m0 + qrow) * 68 + 34 + qcol;
#pragma unroll
        for (int kt = 0; kt < 4; kt++) {
            uint a0 = Au[kt * 8];
            uint a1 = Au[kt * 8 + 8 * 68];
            uint a2 = Au[kt * 8 + 4];
            uint a3 = Au[kt * 8 + 4 + 8 * 68];
            const uint* p0 = pw2 + ((kt * 2 + 0) * 4 + qcol) * 64 + qrow * 8;
            const uint* p1 = pw2 + ((kt * 2 + 1) * 4 + qcol) * 64 + qrow * 8;
            uint B0[8], B1[8];
            *(uint4*)&B0[0] = __ldg((const uint4*)p0);
            *(uint4*)&B0[4] = __ldg((const uint4*)(p0 + 4));
            *(uint4*)&B1[0] = __ldg((const uint4*)p1);
            *(uint4*)&B1[4] = __ldg((const uint4*)(p1 + 4));
#pragma unroll
            for (int nt = 0; nt < 8; nt++)
                mma_bf16(acc2[nt][0], acc2[nt][1], acc2[nt][2], acc2[nt][3],
                         a0, a1, a2, a3, B0[nt], B1[nt]);
        }
    }
    __syncwarp();

    // h = relu(acc2 + b2) -> slab offset 0 (bf16) + g_hb (if not last)
#pragma unroll
    for (int nt = 0; nt < 8; nt++) {
        int c = nt * 8 + qcol * 2;
        float bx = s_b2[c], by = s_b2[c + 1];
        int cp = nt * 4 + qcol;
        int nA = n0 + m0 + qrow;
        int nB = nA + 8;
        uint pA = bpack(fmaxf(acc2[nt][0] + bx, 0.f), fmaxf(acc2[nt][1] + by, 0.f));
        uint pB = bpack(fmaxf(acc2[nt][2] + bx, 0.f), fmaxf(acc2[nt][3] + by, 0.f));
        s_u[(m0 + qrow) * 68 + cp]     = pA;
        s_u[(m0 + qrow + 8) * 68 + cp] = pB;
        if (!is_last) {
            if (nA < N) g_hb[(size_t)nA * 32 + cp] = pA;
            if (nB < N) g_hb[(size_t)nB * 32 + cp] = pB;
        }
    }
    __syncwarp();

    if (has_next) {
        pre_mma(s_u, 68, p_w + (layer + 1) * 12288, msg_b1_next,
                n0, m0, qrow, qcol, N);
        return;
    }

    // ---- fused output head (is_last) ----
    const uint* pw3 = p_w + 3 * 12288;   // out w1 packed (K=64,N=64)
    float acc3[8][4];
#pragma unroll
    for (int nt = 0; nt < 8; nt++)
#pragma unroll
        for (int c = 0; c < 4; c++) acc3[nt][c] = 0.f;
    {
        const uint* Au = s_u + (m0 + qrow) * 68 + qcol;
#pragma unroll
        for (int kt = 0; kt < 4; kt++) {
            uint a0 = Au[kt * 8];
            uint a1 = Au[kt * 8 + 8 * 68];
            uint a2 = Au[kt * 8 + 4];
            uint a3 = Au[kt * 8 + 4 + 8 * 68];
            const uint* p0 = pw3 + ((kt * 2 + 0) * 4 + qcol) * 64 + qrow * 8;
            const uint* p1 = pw3 + ((kt * 2 + 1) * 4 + qcol) * 64 + qrow * 8;
            uint B0[8], B1[8];
            *(uint4*)&B0[0] = __ldg((const uint4*)p0);
            *(uint4*)&B0[4] = __ldg((const uint4*)(p0 + 4));
            *(uint4*)&B1[0] = __ldg((const uint4*)p1);
            *(uint4*)&B1[4] = __ldg((const uint4*)(p1 + 4));
#pragma unroll
            for (int nt = 0; nt < 8; nt++)
                mma_bf16(acc3[nt][0], acc3[nt][1], acc3[nt][2], acc3[nt][3],
                         a0, a1, a2, a3, B0[nt], B1[nt]);
        }
    }

    // partial dots with ow2 [64][3] over this lane's 16 cols, rows A/B
    float pA[3] = {0.f, 0.f, 0.f}, pB[3] = {0.f, 0.f, 0.f};
#pragma unroll
    for (int nt = 0; nt < 8; nt++) {
        int c = nt * 8 + qcol * 2;
        float o1a = s_ob1[c], o1b = s_ob1[c + 1];
        float hA0 = fmaxf(acc3[nt][0] + o1a, 0.f);
        float hA1 = fmaxf(acc3[nt][1] + o1b, 0.f);
        float hB0 = fmaxf(acc3[nt][2] + o1a, 0.f);
        float hB1 = fmaxf(acc3[nt][3] + o1b, 0.f);
#pragma unroll
        for (int cc = 0; cc < 3; cc++) {
            float w0 = s_ow2[c * 3 + cc], w1v = s_ow2[(c + 1) * 3 + cc];
            pA[cc] = fmaf(hA0, w0, fmaf(hA1, w1v, pA[cc]));
            pB[cc] = fmaf(hB0, w0, fmaf(hB1, w1v, pB[cc]));
        }
    }
#pragma unroll
    for (int cc = 0; cc < 3; cc++) {
        pA[cc] += __shfl_xor_sync(0xffffffffu, pA[cc], 1);
        pA[cc] += __shfl_xor_sync(0xffffffffu, pA[cc], 2);
        pB[cc] += __shfl_xor_sync(0xffffffffu, pB[cc], 1);
        pB[cc] += __shfl_xor_sync(0xffffffffu, pB[cc], 2);
    }
    if (qcol == 0) {
        int nA = n0 + m0 + qrow;
        int nB = nA + 8;
        if (nA < N) {
#pragma unroll
            for (int cc = 0; cc < 3; cc++)
                outp[(size_t)nA * 3 + cc] =
                    6.283185307179586f / (1.f + expf(-(pA[cc] + s_ob2[cc])));
        }
        if (nB < N) {
#pragma unroll
            for (int cc = 0; cc < 3; cc++)
                outp[(size_t)nB * 3 + cc] =
                    6.283185307179586f / (1.f + expf(-(pB[cc] + s_ob2[cc])));
        }
    }
}

// ---------------------------------------------------------------------------
extern "C" void kernel_launch(void* const* d_in, const int* in_sizes, int n_in,
                              void* d_out, int out_size)
{
    const float* x      = (const float*)d_in[0];
    const int*   ei     = (const int*)  d_in[1];
    const float* enc_w1 = (const float*)d_in[2];
    const float* enc_b1 = (const float*)d_in[3];
    const float* enc_w2 = (const float*)d_in[4];
    const float* enc_b2 = (const float*)d_in[5];
    const float* msg_w1 = (const float*)d_in[6];
    const float* msg_b1 = (const float*)d_in[7];
    const float* msg_w2 = (const float*)d_in[8];
    const float* msg_b2 = (const float*)d_in[9];
    const float* upd_w1 = (const float*)d_in[10];
    const float* upd_b1 = (const float*)d_in[11];
    const float* upd_w2 = (const float*)d_in[12];
    const float* upd_b2 = (const float*)d_in[13];
    const float* out_w1 = (const float*)d_in[14];
    const float* out_b1 = (const float*)d_in[15];
    const float* out_w2 = (const float*)d_in[16];
    const float* out_b2 = (const float*)d_in[17];

    int N = in_sizes[0] / 5;
    int E = in_sizes[1] / 2;
    if (N > NMAX) N = NMAX;
    if (E > EMAX) E = EMAX;
    const int* src = ei;
    const int* dstp = ei + E;

    const int ENC_SM = (128 * 65 + 64 * 64) * 4;    // 49664
    cudaFuncSetAttribute(k_encoder, cudaFuncAttributeMaxDynamicSharedMemorySize, ENC_SM);

    int nbE256 = (E + 255) / 256;
    int nbN128 = (N + 127) / 128;
    int nbE128 = (E + 127) / 128;

    k_pack<<<(PACKN + N + 255) / 256, 256>>>(msg_w1, msg_w2, upd_w1, upd_w2,
                                             out_w1, N);
    k_count<<<nbE256, 256>>>(dstp, E);
    k_encoder<<<nbN128, 256, ENC_SM>>>(x, enc_w1, enc_b1, enc_w2, enc_b2,
                                       msg_b1, N);

    for (int l = 0; l < 3; l++) {
        k_edge<<<nbE128, 256>>>(src, dstp, l, msg_b2 + l * 64, E);
        k_upd<<<nbN128, 256>>>(l, upd_b1 + l * 64, upd_b2 + l * 64,
                               (l < 2) ? 1 : 0, msg_b1 + (l + 1) * 64,
                               out_b1, out_w2, out_b2, (float*)d_out, N);
    }
}